// round 2
// baseline (speedup 1.0000x reference)
#include <cuda_runtime.h>
#include <math.h>

typedef unsigned long long ull;

// Problem constants
constexpr int Bc   = 2;
constexpr int Lc   = 1000;
constexpr int Dc   = 288;
constexpr int Hc   = 8;
constexpr int DIMc = 36;
constexpr int DFFc = 576;
constexpr int KSc  = 250;
constexpr int NQc  = 250;
constexpr int BHc  = Bc * Hc;      // 16
constexpr int Mrows = Bc * Lc;     // 2000

// Scratch (static device globals; no allocation)
__device__ float g_qf[BHc * Lc * DIMc];
__device__ float g_kf[BHc * Lc * DIMc];
__device__ float g_vf[BHc * Lc * DIMc];
__device__ float g_measure[BHc * Lc];
__device__ int   g_idxq[BHc * NQc];
__device__ float g_sim[BHc * NQc * Lc];          // raw sim -> probabilities (in place)
__device__ float g_av[2 * BHc * NQc * DIMc];     // split-k slabs
__device__ float g_vmean[BHc * DIMc];
__device__ float g_attn[Bc * Lc * Dc];
__device__ float g_h1f[Bc * Lc * Dc];
__device__ float g_f1f[Bc * Lc * DFFc];
__device__ float g_f2f[Bc * Lc * Dc];

__device__ __forceinline__ float gelu_exact(float x) {
    return 0.5f * x * (1.0f + erff(x * 0.7071067811865475f));
}

// ---------------------------------------------------------------------------
// Packed-FFMA2 tiled GEMM: C[M,N] = A[M,K] @ W^T (+bias, epilogue per MODE)
// MODE 0: QKV (N=864 : Wq|Wk|Wv), scatter to g_qf/g_kf/g_vf in [bh][l][d]
// MODE 1: FFN1: A=g_h1f, gelu -> g_f1f
// MODE 2: FFN2: A=g_f1f, gelu -> g_f2f
// BM=128, BN=64/32, BK=16, 256 threads, 8xCPT outputs per thread.
// Accumulators are f32x2 pairs along M; B is stored duplicated (b,b) in an
// interleaved slot layout so both operands are conflict-free LDS.64 reads.
// ---------------------------------------------------------------------------
template <int MODE, int BN>
__global__ void __launch_bounds__(256) gemm2(
    const float* __restrict__ A_in, int M, int N, int K,
    const float* __restrict__ W0, const float* __restrict__ W1p,
    const float* __restrict__ W2p,
    const float* __restrict__ b0, const float* __restrict__ b1p,
    const float* __restrict__ b2p)
{
    constexpr int CPT  = BN / 16;       // cols per thread (4 or 2)
    constexpr int BSTR = 2 * BN + 2;    // duplicated-B row stride (even)

    const float* A = (MODE == 0) ? A_in : (MODE == 1 ? g_h1f : g_f1f);

    __shared__ __align__(16) float As[16][132];
    __shared__ __align__(16) float Bs[16][BSTR];

    const int m0 = blockIdx.y * 128;
    const int n0 = blockIdx.x * BN;
    const int tid = threadIdx.x;
    const int tx = tid & 15;    // column group
    const int ty = tid >> 4;    // row group (8 rows)

    ull acc[4][CPT];
#pragma unroll
    for (int p = 0; p < 4; p++)
#pragma unroll
        for (int j = 0; j < CPT; j++) acc[p][j] = 0ULL;

    const int ktiles = K / 16;
    for (int kt = 0; kt < ktiles; kt++) {
        const int k0 = kt * 16;

        // --- load A tile: 16 x 128 ---
#pragma unroll
        for (int p = 0; p < 8; p++) {
            int i  = tid + p * 256;
            int kk = i & 15;
            int mi = i >> 4;
            int r  = m0 + mi;
            As[kk][mi] = (r < M) ? A[r * K + k0 + kk] : 0.0f;
        }
        // --- load B tile duplicated: 16 x BN -> slots ---
#pragma unroll
        for (int p = 0; p < BN / 16; p++) {
            int i  = tid + p * 256;
            int kk = i & 15;
            int nc = i >> 4;
            int col = n0 + nc;
            float wv = 0.0f;
            if (col < N) {
                if (MODE == 0) {
                    const float* w; int cc;
                    if (col < 288)      { w = W0;  cc = col; }
                    else if (col < 576) { w = W1p; cc = col - 288; }
                    else                { w = W2p; cc = col - 576; }
                    wv = w[cc * K + k0 + kk];
                } else {
                    wv = W0[col * K + k0 + kk];
                }
            }
            int s = (nc % CPT) * 16 + (nc / CPT);
            *(float2*)&Bs[kk][2 * s] = make_float2(wv, wv);
        }
        __syncthreads();

#pragma unroll 4
        for (int kk = 0; kk < 16; kk++) {
            ull ap[4], bd[CPT];
#pragma unroll
            for (int p = 0; p < 4; p++)
                ap[p] = *(const ull*)&As[kk][ty * 8 + 2 * p];
#pragma unroll
            for (int j = 0; j < CPT; j++)
                bd[j] = *(const ull*)&Bs[kk][2 * (j * 16 + tx)];
#pragma unroll
            for (int p = 0; p < 4; p++)
#pragma unroll
                for (int j = 0; j < CPT; j++)
                    asm("fma.rn.f32x2 %0, %1, %2, %0;"
                        : "+l"(acc[p][j]) : "l"(ap[p]), "l"(bd[j]));
        }
        __syncthreads();
    }

    // epilogue
#pragma unroll
    for (int p = 0; p < 4; p++) {
#pragma unroll
        for (int j = 0; j < CPT; j++) {
            int col = n0 + tx * CPT + j;
            if (col >= N) continue;
            float vlo = __uint_as_float((unsigned)(acc[p][j] & 0xffffffffULL));
            float vhi = __uint_as_float((unsigned)(acc[p][j] >> 32));
#pragma unroll
            for (int hfl = 0; hfl < 2; hfl++) {
                int r = m0 + ty * 8 + 2 * p + hfl;
                if (r >= M) continue;
                float v = hfl ? vhi : vlo;
                if (MODE == 0) {
                    int cc; const float* bias; float* dst;
                    if (col < 288)      { cc = col;       bias = b0;  dst = g_qf; }
                    else if (col < 576) { cc = col - 288; bias = b1p; dst = g_kf; }
                    else                { cc = col - 576; bias = b2p; dst = g_vf; }
                    v += bias[cc];
                    int h  = cc / 36;
                    int dd = cc - h * 36;
                    int bb = r / Lc;
                    int ll = r - bb * Lc;
                    dst[((bb * Hc + h) * Lc + ll) * DIMc + dd] = v;
                } else {
                    v = gelu_exact(v + b1p[col]);
                    if (MODE == 1) g_f1f[r * N + col] = v;
                    else           g_f2f[r * N + col] = v;
                }
            }
        }
    }
}

// ---------------------------------------------------------------------------
// Measure kernel: measure[bh][l] = max_j q.k[idx] - sum_j(q.k[idx]) / L
// K[bh] staged in dynamic smem (stride 37 to decorrelate banks).
// grid (16 chunks, 16 bh), 256 threads, warp-per-query.
// ---------------------------------------------------------------------------
__global__ void __launch_bounds__(256) measure_kernel(const int* __restrict__ ik)
{
    extern __shared__ float ks[];   // [Lc][37]
    const int chunk = blockIdx.x;
    const int bh    = blockIdx.y;
    const int tid   = threadIdx.x;

    const float* ksrc = &g_kf[bh * Lc * DIMc];
    for (int i = tid; i < Lc * DIMc; i += 256) {
        int l = i / DIMc;
        int d = i - l * DIMc;
        ks[l * 37 + d] = ksrc[i];
    }
    __syncthreads();

    const int warp = tid >> 5;
    const int lane = tid & 31;
    const int lstart = chunk * 63;
    const int lend   = min(lstart + 63, Lc);

    for (int l = lstart + warp; l < lend; l += 8) {
        float qr[36];
        const float4* qp = (const float4*)&g_qf[(bh * Lc + l) * DIMc];
#pragma unroll
        for (int c = 0; c < 9; c++) {
            float4 t = qp[c];
            qr[c * 4 + 0] = t.x; qr[c * 4 + 1] = t.y;
            qr[c * 4 + 2] = t.z; qr[c * 4 + 3] = t.w;
        }
        float mx = -3.4e38f;
        float sm = 0.0f;
#pragma unroll
        for (int jj = 0; jj < 8; jj++) {
            int j = lane + jj * 32;
            if (j < KSc) {
                int idx = ik[l * KSc + j];
                const float* kp = &ks[idx * 37];
                float accd = 0.0f;
#pragma unroll
                for (int d = 0; d < 36; d++) accd += qr[d] * kp[d];
                mx = fmaxf(mx, accd);
                sm += accd;
            }
        }
#pragma unroll
        for (int o = 16; o; o >>= 1) {
            mx = fmaxf(mx, __shfl_xor_sync(0xffffffffu, mx, o));
            sm += __shfl_xor_sync(0xffffffffu, sm, o);
        }
        if (lane == 0) g_measure[bh * Lc + l] = mx - sm * (1.0f / (float)Lc);
    }
}

// ---------------------------------------------------------------------------
// TopK: per bh, top-250 of 1000 measures via bitonic sort of packed u64 keys.
// key = (orderable_float << 32) | ~index  -> descending sort gives exact
// jax.lax.top_k semantics (value desc, index asc on ties).
// ---------------------------------------------------------------------------
__global__ void __launch_bounds__(512) topk_kernel()
{
    __shared__ unsigned long long keys[1024];
    const int bh  = blockIdx.x;
    const int tid = threadIdx.x;

    for (int i = tid; i < 1024; i += 512) {
        unsigned long long kv = 0ULL;
        if (i < Lc) {
            float f = g_measure[bh * Lc + i];
            unsigned u = __float_as_uint(f);
            u = (u & 0x80000000u) ? ~u : (u | 0x80000000u);
            kv = ((unsigned long long)u << 32) | (unsigned)(~i);
        }
        keys[i] = kv;
    }
    __syncthreads();

    for (int k = 2; k <= 1024; k <<= 1) {
        for (int j = k >> 1; j > 0; j >>= 1) {
#pragma unroll
            for (int w = 0; w < 2; w++) {
                int i   = tid + w * 512;
                int ixj = i ^ j;
                if (ixj > i) {
                    bool descend = ((i & k) == 0);
                    unsigned long long a = keys[i];
                    unsigned long long b = keys[ixj];
                    bool sw = descend ? (a < b) : (a > b);
                    if (sw) { keys[i] = b; keys[ixj] = a; }
                }
            }
            __syncthreads();
        }
    }

    if (tid < NQc) {
        unsigned low = (unsigned)keys[tid];
        g_idxq[bh * NQc + tid] = (int)(~low);
    }
}

// ---------------------------------------------------------------------------
// Selected-query sim GEMM: sim[bh][q][k] = (1/6) * q_sel . k
// block: 64 queries x 64 keys, K=36 in smem. grid (16 kt, 4 qt, 16 bh).
// ---------------------------------------------------------------------------
__global__ void __launch_bounds__(256) sim_kernel()
{
    __shared__ float Qs[36][68];
    __shared__ float Ks[36][68];
    const int bh = blockIdx.z;
    const int n0 = blockIdx.x * 64;
    const int m0 = blockIdx.y * 64;
    const int tid = threadIdx.x;

    for (int i = tid; i < 64 * 36; i += 256) {
        int qi = i / 36;
        int d  = i - qi * 36;
        float qv = 0.0f;
        int q = m0 + qi;
        if (q < NQc) {
            int row = g_idxq[bh * NQc + q];
            qv = g_qf[(bh * Lc + row) * DIMc + d];
        }
        Qs[d][qi] = qv;
        int kx = n0 + qi;
        Ks[d][qi] = (kx < Lc) ? g_kf[(bh * Lc + kx) * DIMc + d] : 0.0f;
    }
    __syncthreads();

    const int tx = tid & 15;
    const int ty = tid >> 4;
    float acc[4][4];
#pragma unroll
    for (int i = 0; i < 4; i++)
#pragma unroll
        for (int j = 0; j < 4; j++) acc[i][j] = 0.0f;

#pragma unroll
    for (int d = 0; d < 36; d++) {
        float4 av4 = *(const float4*)&Qs[d][ty * 4];
        float4 bv4 = *(const float4*)&Ks[d][tx * 4];
        float ar[4] = {av4.x, av4.y, av4.z, av4.w};
        float br[4] = {bv4.x, bv4.y, bv4.z, bv4.w};
#pragma unroll
        for (int i = 0; i < 4; i++)
#pragma unroll
            for (int j = 0; j < 4; j++) acc[i][j] += ar[i] * br[j];
    }

#pragma unroll
    for (int i = 0; i < 4; i++) {
        int q = m0 + ty * 4 + i;
        if (q >= NQc) continue;
#pragma unroll
        for (int j = 0; j < 4; j++) {
            int kx = n0 + tx * 4 + j;
            if (kx >= Lc) continue;
            g_sim[(bh * NQc + q) * Lc + kx] = acc[i][j] * (1.0f / 6.0f);
        }
    }
}

// ---------------------------------------------------------------------------
// Row softmax over 1000 keys, in place in g_sim. grid (250, 16), 256 threads.
// ---------------------------------------------------------------------------
__global__ void __launch_bounds__(256) softmax_kernel()
{
    const int bh = blockIdx.y;
    const int q  = blockIdx.x;
    float* row = &g_sim[(bh * NQc + q) * Lc];
    const int tid = threadIdx.x;
    __shared__ float red[8];
    __shared__ float s_m, s_inv;

    float mx = -3.4e38f;
    for (int j = tid; j < Lc; j += 256) mx = fmaxf(mx, row[j]);
#pragma unroll
    for (int o = 16; o; o >>= 1) mx = fmaxf(mx, __shfl_xor_sync(0xffffffffu, mx, o));
    if ((tid & 31) == 0) red[tid >> 5] = mx;
    __syncthreads();
    if (tid == 0) {
        float t = red[0];
        for (int i = 1; i < 8; i++) t = fmaxf(t, red[i]);
        s_m = t;
    }
    __syncthreads();

    float sum = 0.0f;
    for (int j = tid; j < Lc; j += 256) {
        float e = __expf(row[j] - s_m);
        row[j] = e;
        sum += e;
    }
#pragma unroll
    for (int o = 16; o; o >>= 1) sum += __shfl_xor_sync(0xffffffffu, sum, o);
    if ((tid & 31) == 0) red[tid >> 5] = sum;
    __syncthreads();
    if (tid == 0) {
        float t = 0.0f;
        for (int i = 0; i < 8; i++) t += red[i];
        s_inv = 1.0f / t;
    }
    __syncthreads();

    float inv = s_inv;
    for (int j = tid; j < Lc; j += 256) row[j] *= inv;
}

// ---------------------------------------------------------------------------
// V mean per (bh), deterministic tree reduction. grid 16, 256 threads.
// ---------------------------------------------------------------------------
__global__ void __launch_bounds__(256) vmean_kernel()
{
    const int bh  = blockIdx.x;
    const int tid = threadIdx.x;
    float acc[36];
#pragma unroll
    for (int d = 0; d < 36; d++) acc[d] = 0.0f;

    for (int l = tid; l < Lc; l += 256) {
        const float* vp = &g_vf[(bh * Lc + l) * DIMc];
#pragma unroll
        for (int d = 0; d < 36; d++) acc[d] += vp[d];
    }
#pragma unroll
    for (int d = 0; d < 36; d++) {
#pragma unroll
        for (int o = 16; o; o >>= 1) acc[d] += __shfl_xor_sync(0xffffffffu, acc[d], o);
    }
    __shared__ float sm[8][36];
    if ((tid & 31) == 0) {
        int w = tid >> 5;
#pragma unroll
        for (int d = 0; d < 36; d++) sm[w][d] = acc[d];
    }
    __syncthreads();
    if (tid < 36) {
        float t = 0.0f;
#pragma unroll
        for (int w = 0; w < 8; w++) t += sm[w][tid];
        g_vmean[bh * DIMc + tid] = t * (1.0f / (float)Lc);
    }
}

// Fill attn output with per-head mean(V)
__global__ void __launch_bounds__(256) fill_kernel()
{
    int i = blockIdx.x * 256 + threadIdx.x;
    if (i >= Bc * Lc * Dc) return;
    int d  = i % Dc;
    int bl = i / Dc;
    int b  = bl / Lc;
    int hh = d / 36;
    int dd = d - hh * 36;
    g_attn[i] = g_vmean[(b * Hc + hh) * DIMc + dd];
}

// ---------------------------------------------------------------------------
// AV GEMM: out_sel[250,36] = P[250,1000] @ V[1000,36], split-K=2 (determin.)
// grid (4 qt, 16 bh, 2 split), 144 threads, 4x4 tiles.
// ---------------------------------------------------------------------------
__global__ void __launch_bounds__(144) av_kernel()
{
    __shared__ float Ps[16][68];
    __shared__ float Vs[16][40];
    const int m0    = blockIdx.x * 64;
    const int bh    = blockIdx.y;
    const int split = blockIdx.z;
    const int tid   = threadIdx.x;
    const int tx = tid % 16;   // q quad
    const int ty = tid / 16;   // d quad (0..8)

    float acc[4][4];
#pragma unroll
    for (int i = 0; i < 4; i++)
#pragma unroll
        for (int j = 0; j < 4; j++) acc[i][j] = 0.0f;

    for (int kt = 0; kt < 32; kt++) {
        int k0 = split * 512 + kt * 16;
        for (int i = tid; i < 1024; i += 144) {
            int kk = i & 15;
            int qi = i >> 4;
            int q = m0 + qi, k = k0 + kk;
            Ps[kk][qi] = (q < NQc && k < Lc) ? g_sim[(bh * NQc + q) * Lc + k] : 0.0f;
        }
        for (int i = tid; i < 16 * 36; i += 144) {
            int d  = i % 36;
            int kk = i / 36;
            int k = k0 + kk;
            Vs[kk][d] = (k < Lc) ? g_vf[(bh * Lc + k) * DIMc + d] : 0.0f;
        }
        __syncthreads();
#pragma unroll
        for (int kk = 0; kk < 16; kk++) {
            float4 pv4 = *(const float4*)&Ps[kk][tx * 4];
            float4 vv4 = *(const float4*)&Vs[kk][ty * 4];
            float pr[4] = {pv4.x, pv4.y, pv4.z, pv4.w};
            float vr[4] = {vv4.x, vv4.y, vv4.z, vv4.w};
#pragma unroll
            for (int i = 0; i < 4; i++)
#pragma unroll
                for (int j = 0; j < 4; j++) acc[i][j] += pr[i] * vr[j];
        }
        __syncthreads();
    }

#pragma unroll
    for (int i = 0; i < 4; i++) {
        int q = m0 + tx * 4 + i;
        if (q >= NQc) continue;
#pragma unroll
        for (int j = 0; j < 4; j++) {
            int d = ty * 4 + j;
            g_av[((split * BHc + bh) * NQc + q) * DIMc + d] = acc[i][j];
        }
    }
}

// Scatter active-query outputs into g_attn (sum of split-k slabs)
__global__ void __launch_bounds__(256) scatter_kernel()
{
    int i = blockIdx.x * 256 + threadIdx.x;
    if (i >= BHc * NQc * DIMc) return;
    int d = i % DIMc;
    int t = i / DIMc;
    int q  = t % NQc;
    int bh = t / NQc;
    int l = g_idxq[bh * NQc + q];
    float val = g_av[((0 * BHc + bh) * NQc + q) * DIMc + d]
              + g_av[((1 * BHc + bh) * NQc + q) * DIMc + d];
    int b = bh >> 3;
    int h = bh & 7;
    g_attn[(b * Lc + l) * Dc + h * 36 + d] = val;
}

// ---------------------------------------------------------------------------
// LayerNorm over D=288: out = LN(a + b). WHICH 0: a=x(param), out=g_h1f.
// WHICH 1: a=g_f2f, b=g_h1f, out=param. grid 2000, 288 threads.
// ---------------------------------------------------------------------------
template <int WHICH>
__global__ void __launch_bounds__(288) ln_kernel(
    const float* __restrict__ xin, float* __restrict__ oout,
    const float* __restrict__ gg, const float* __restrict__ bb)
{
    const int r = blockIdx.x;
    const int d = threadIdx.x;
    const int base = r * Dc;

    float v;
    if (WHICH == 0) v = xin[base + d] + g_attn[base + d];
    else            v = g_f2f[base + d] + g_h1f[base + d];

    __shared__ float red[9];
    __shared__ float s_mu, s_rs;

    float s = v;
#pragma unroll
    for (int o = 16; o; o >>= 1) s += __shfl_xor_sync(0xffffffffu, s, o);
    if ((d & 31) == 0) red[d >> 5] = s;
    __syncthreads();
    if (d == 0) {
        float t = 0.0f;
        for (int i = 0; i < 9; i++) t += red[i];
        s_mu = t * (1.0f / (float)Dc);
    }
    __syncthreads();

    float dv = v - s_mu;
    float qv = dv * dv;
#pragma unroll
    for (int o = 16; o; o >>= 1) qv += __shfl_xor_sync(0xffffffffu, qv, o);
    if ((d & 31) == 0) red[d >> 5] = qv;
    __syncthreads();
    if (d == 0) {
        float t = 0.0f;
        for (int i = 0; i < 9; i++) t += red[i];
        s_rs = rsqrtf(t * (1.0f / (float)Dc) + 1e-5f);
    }
    __syncthreads();

    float outv = dv * s_rs * gg[d] + bb[d];
    if (WHICH == 0) g_h1f[base + d] = outv;
    else            oout[base + d]  = outv;
}

// ---------------------------------------------------------------------------
extern "C" void kernel_launch(void* const* d_in, const int* in_sizes, int n_in,
                              void* d_out, int out_size)
{
    (void)in_sizes; (void)n_in; (void)out_size;
    const float* x   = (const float*)d_in[0];
    const int*   ik  = (const int*)d_in[1];
    const float* Wq  = (const float*)d_in[2];
    const float* bq  = (const float*)d_in[3];
    const float* Wk  = (const float*)d_in[4];
    const float* bk  = (const float*)d_in[5];
    const float* Wv  = (const float*)d_in[6];
    const float* bv  = (const float*)d_in[7];
    const float* W1  = (const float*)d_in[8];
    const float* b1  = (const float*)d_in[9];
    const float* W2  = (const float*)d_in[10];
    const float* b2  = (const float*)d_in[11];
    const float* g1  = (const float*)d_in[12];
    const float* be1 = (const float*)d_in[13];
    const float* g2  = (const float*)d_in[14];
    const float* be2 = (const float*)d_in[15];
    float* out = (float*)d_out;

    const int measure_smem = Lc * 37 * (int)sizeof(float);  // 148 KB
    cudaFuncSetAttribute(measure_kernel,
                         cudaFuncAttributeMaxDynamicSharedMemorySize, measure_smem);

    // 1) QKV projections (N=864, K=288)
    gemm2<0, 64><<<dim3((864 + 63) / 64, (Mrows + 127) / 128), 256>>>(
        x, Mrows, 864, Dc, Wq, Wk, Wv, bq, bk, bv);

    // 2) sparsity measure
    measure_kernel<<<dim3(16, BHc), 256, measure_smem>>>(ik);

    // 3) top-250 active queries per (b,h)
    topk_kernel<<<BHc, 512>>>();

    // 4) sim for selected queries
    sim_kernel<<<dim3(16, 4, BHc), 256>>>();

    // 5) softmax rows
    softmax_kernel<<<dim3(NQc, BHc), 256>>>();

    // 6) mean(V) + lazy fill
    vmean_kernel<<<BHc, 256>>>();
    fill_kernel<<<(Bc * Lc * Dc + 255) / 256, 256>>>();

    // 7) attn @ V (split-k = 2), then scatter active outputs
    av_kernel<<<dim3(4, BHc, 2), 144>>>();
    scatter_kernel<<<(BHc * NQc * DIMc + 255) / 256, 256>>>();

    // 8) residual + LN1
    ln_kernel<0><<<Mrows, 288>>>(x, nullptr, g1, be1);

    // 9) FFN (exact GELU both layers)
    gemm2<1, 64><<<dim3((DFFc + 63) / 64, (Mrows + 127) / 128), 256>>>(
        nullptr, Mrows, DFFc, Dc, W1, nullptr, nullptr, nullptr, b1, nullptr);
    gemm2<2, 32><<<dim3((Dc + 31) / 32, (Mrows + 127) / 128), 256>>>(
        nullptr, Mrows, Dc, DFFc, W2, nullptr, nullptr, nullptr, b2, nullptr);

    // 10) residual + LN2 -> output
    ln_kernel<1><<<Mrows, 288>>>(nullptr, out, g2, be2);
}

// round 3
// speedup vs baseline: 1.2228x; 1.2228x over previous
#include <cuda_runtime.h>
#include <math.h>

// Problem constants
constexpr int Bc   = 2;
constexpr int Lc   = 1000;
constexpr int Dc   = 288;
constexpr int Hc   = 8;
constexpr int DIMc = 36;
constexpr int DFFc = 576;
constexpr int KSc  = 250;
constexpr int NQc  = 250;
constexpr int BHc  = Bc * Hc;      // 16
constexpr int Mrows = Bc * Lc;     // 2000

// Scratch (static device globals; no allocation)
__device__ float g_qf[BHc * Lc * DIMc];
__device__ float g_kf[BHc * Lc * DIMc];
__device__ float g_vf[BHc * Lc * DIMc];
__device__ float g_measure[BHc * Lc];
__device__ int   g_idxq[BHc * NQc];
__device__ float g_sim[BHc * NQc * Lc];          // raw sim -> probabilities (in place)
__device__ float g_av[2 * BHc * NQc * DIMc];     // split-k slabs
__device__ float g_vmean[BHc * DIMc];
__device__ float g_attn[Bc * Lc * Dc];
__device__ float g_h1f[Bc * Lc * Dc];
__device__ float g_f1f[Bc * Lc * DFFc];
__device__ float g_f2f[Bc * Lc * Dc];

__device__ __forceinline__ float gelu_exact(float x) {
    return 0.5f * x * (1.0f + erff(x * 0.7071067811865475f));
}

// ---------------------------------------------------------------------------
// Tiled GEMM: C[M,N] = A[M,K] @ W^T (+bias, epilogue per MODE)
// MODE 0: QKV (N=864 : Wq|Wk|Wv), scatter to g_qf/g_kf/g_vf in [bh][l][d]
// MODE 1: FFN1: A=g_h1f, gelu -> g_f1f
// MODE 2: FFN2: A=g_f1f, gelu -> g_f2f
// BM=128, BN in {32,64}, BK=16, 256 threads, 8 x (BN/16) outputs per thread.
// Issue mix per kk: 2 LDS.128 (A) + 1 LDS.128/.64 (B) + 8*TN FFMA.
// ---------------------------------------------------------------------------
template <int MODE, int BN>
__global__ void __launch_bounds__(256) gemm3(
    const float* __restrict__ A_in, int M, int N, int K,
    const float* __restrict__ W0, const float* __restrict__ W1p,
    const float* __restrict__ W2p,
    const float* __restrict__ b0, const float* __restrict__ b1p,
    const float* __restrict__ b2p)
{
    constexpr int TN   = BN / 16;       // cols per thread (2 or 4)
    constexpr int BSTR = BN + 4;        // padded B row stride

    const float* A = (MODE == 0) ? A_in : (MODE == 1 ? g_h1f : g_f1f);

    __shared__ __align__(16) float As[16][132];
    __shared__ __align__(16) float Bs[16][BSTR];

    const int m0 = blockIdx.y * 128;
    const int n0 = blockIdx.x * BN;
    const int tid = threadIdx.x;
    const int tx = tid & 15;    // column group
    const int ty = tid >> 4;    // row group (8 rows each)

    float acc[8][TN];
#pragma unroll
    for (int i = 0; i < 8; i++)
#pragma unroll
        for (int j = 0; j < TN; j++) acc[i][j] = 0.0f;

    const int ktiles = K / 16;
    for (int kt = 0; kt < ktiles; kt++) {
        const int k0 = kt * 16;

        // load A tile 128x16
#pragma unroll
        for (int p = 0; p < 8; p++) {
            int i  = tid + p * 256;
            int kk = i & 15;
            int mi = i >> 4;
            int r  = m0 + mi;
            As[kk][mi] = (r < M) ? A[r * K + k0 + kk] : 0.0f;
        }
        // load B tile BNx16 (W is [N,K] row-major)
#pragma unroll
        for (int p = 0; p < BN / 16; p++) {
            int i  = tid + p * 256;
            int kk = i & 15;
            int nc = i >> 4;
            int col = n0 + nc;
            float wv = 0.0f;
            if (col < N) {
                if (MODE == 0) {
                    const float* w; int cc;
                    if (col < 288)      { w = W0;  cc = col; }
                    else if (col < 576) { w = W1p; cc = col - 288; }
                    else                { w = W2p; cc = col - 576; }
                    wv = w[cc * K + k0 + kk];
                } else {
                    wv = W0[col * K + k0 + kk];
                }
            }
            Bs[kk][nc] = wv;
        }
        __syncthreads();

#pragma unroll
        for (int kk = 0; kk < 16; kk++) {
            float a8[8];
            float4 a0 = *(const float4*)&As[kk][ty * 8];
            float4 a1 = *(const float4*)&As[kk][ty * 8 + 4];
            a8[0] = a0.x; a8[1] = a0.y; a8[2] = a0.z; a8[3] = a0.w;
            a8[4] = a1.x; a8[5] = a1.y; a8[6] = a1.z; a8[7] = a1.w;
            float bv[TN];
            if (TN == 4) {
                float4 b4 = *(const float4*)&Bs[kk][tx * 4];
                bv[0] = b4.x; bv[1] = b4.y; bv[2] = b4.z; bv[3] = b4.w;
            } else {
                float2 b2v = *(const float2*)&Bs[kk][tx * 2];
                bv[0] = b2v.x; bv[1] = b2v.y;
            }
#pragma unroll
            for (int i = 0; i < 8; i++)
#pragma unroll
                for (int j = 0; j < TN; j++) acc[i][j] += a8[i] * bv[j];
        }
        __syncthreads();
    }

    // epilogue
#pragma unroll
    for (int i = 0; i < 8; i++) {
        int r = m0 + ty * 8 + i;
        if (r >= M) continue;
#pragma unroll
        for (int j = 0; j < TN; j++) {
            int col = n0 + tx * TN + j;
            if (col >= N) continue;
            float v = acc[i][j];
            if (MODE == 0) {
                int cc; const float* bias; float* dst;
                if (col < 288)      { cc = col;       bias = b0;  dst = g_qf; }
                else if (col < 576) { cc = col - 288; bias = b1p; dst = g_kf; }
                else                { cc = col - 576; bias = b2p; dst = g_vf; }
                v += bias[cc];
                int h  = cc / 36;
                int dd = cc - h * 36;
                int bb = r / Lc;
                int ll = r - bb * Lc;
                dst[((bb * Hc + h) * Lc + ll) * DIMc + dd] = v;
            } else {
                v = gelu_exact(v + b1p[col]);
                if (MODE == 1) g_f1f[r * N + col] = v;
                else           g_f2f[r * N + col] = v;
            }
        }
    }
}

// ---------------------------------------------------------------------------
// Measure kernel: measure[bh][l] = max_j q.k[idx] - sum_j(q.k[idx]) / L
// K[bh] staged in dynamic smem natural layout (144B rows, float4 aligned).
// grid (9 chunks, 16 bh) = 144 blocks = 1 wave at 1 CTA/SM. 256 threads,
// warp-per-query, float4 smem reads (quad-granular conflicts only).
// ---------------------------------------------------------------------------
__global__ void __launch_bounds__(256) measure_kernel(const int* __restrict__ ik)
{
    extern __shared__ __align__(16) float ks[];   // [Lc][36]
    const int chunk = blockIdx.x;
    const int bh    = blockIdx.y;
    const int tid   = threadIdx.x;

    // stage K[bh]: straight float4 copy (identical layout)
    const float4* ksrc4 = (const float4*)&g_kf[bh * Lc * DIMc];
    float4* kdst4 = (float4*)ks;
    for (int i = tid; i < Lc * DIMc / 4; i += 256) kdst4[i] = ksrc4[i];
    __syncthreads();

    const int warp = tid >> 5;
    const int lane = tid & 31;
    const int lstart = chunk * 112;
    const int lend   = min(lstart + 112, Lc);

    for (int l = lstart + warp; l < lend; l += 8) {
        float4 q4[9];
        const float4* qp = (const float4*)&g_qf[(bh * Lc + l) * DIMc];
#pragma unroll
        for (int c = 0; c < 9; c++) q4[c] = qp[c];

        float mx = -3.4e38f;
        float sm = 0.0f;
#pragma unroll
        for (int jj = 0; jj < 8; jj++) {
            int j = lane + jj * 32;
            if (j < KSc) {
                int idx = ik[l * KSc + j];
                const float4* kp = (const float4*)&ks[idx * DIMc];
                float accd = 0.0f;
#pragma unroll
                for (int c = 0; c < 9; c++) {
                    float4 kv = kp[c];
                    accd += q4[c].x * kv.x + q4[c].y * kv.y
                          + q4[c].z * kv.z + q4[c].w * kv.w;
                }
                mx = fmaxf(mx, accd);
                sm += accd;
            }
        }
#pragma unroll
        for (int o = 16; o; o >>= 1) {
            mx = fmaxf(mx, __shfl_xor_sync(0xffffffffu, mx, o));
            sm += __shfl_xor_sync(0xffffffffu, sm, o);
        }
        if (lane == 0) g_measure[bh * Lc + l] = mx - sm * (1.0f / (float)Lc);
    }
}

// ---------------------------------------------------------------------------
// TopK: per bh, top-250 of 1000 measures via bitonic sort of packed u64 keys.
// ---------------------------------------------------------------------------
__global__ void __launch_bounds__(512) topk_kernel()
{
    __shared__ unsigned long long keys[1024];
    const int bh  = blockIdx.x;
    const int tid = threadIdx.x;

    for (int i = tid; i < 1024; i += 512) {
        unsigned long long kv = 0ULL;
        if (i < Lc) {
            float f = g_measure[bh * Lc + i];
            unsigned u = __float_as_uint(f);
            u = (u & 0x80000000u) ? ~u : (u | 0x80000000u);
            kv = ((unsigned long long)u << 32) | (unsigned)(~i);
        }
        keys[i] = kv;
    }
    __syncthreads();

    for (int k = 2; k <= 1024; k <<= 1) {
        for (int j = k >> 1; j > 0; j >>= 1) {
#pragma unroll
            for (int w = 0; w < 2; w++) {
                int i   = tid + w * 512;
                int ixj = i ^ j;
                if (ixj > i) {
                    bool descend = ((i & k) == 0);
                    unsigned long long a = keys[i];
                    unsigned long long b = keys[ixj];
                    bool sw = descend ? (a < b) : (a > b);
                    if (sw) { keys[i] = b; keys[ixj] = a; }
                }
            }
            __syncthreads();
        }
    }

    if (tid < NQc) {
        unsigned low = (unsigned)keys[tid];
        g_idxq[bh * NQc + tid] = (int)(~low);
    }
}

// ---------------------------------------------------------------------------
// Selected-query sim GEMM: sim[bh][q][k] = (1/6) * q_sel . k
// block: 64 queries x 64 keys. float4 staging; grid (16 kt, 4 qt, 16 bh).
// ---------------------------------------------------------------------------
__global__ void __launch_bounds__(256) sim_kernel()
{
    __shared__ float Qs[36][68];
    __shared__ float Ks[36][68];
    __shared__ int   qidx[64];
    const int bh = blockIdx.z;
    const int n0 = blockIdx.x * 64;
    const int m0 = blockIdx.y * 64;
    const int tid = threadIdx.x;

    if (tid < 64) {
        int q = m0 + tid;
        qidx[tid] = (q < NQc) ? g_idxq[bh * NQc + q] : 0;
    }
    __syncthreads();

    // 64 rows x 9 float4 each = 576 float4 per operand
    for (int i = tid; i < 576; i += 256) {
        int qi = i / 9;
        int c  = i - qi * 9;
        int q = m0 + qi;
        float4 qv = make_float4(0.f, 0.f, 0.f, 0.f);
        if (q < NQc) {
            int row = qidx[qi];
            qv = *(const float4*)&g_qf[(bh * Lc + row) * DIMc + c * 4];
        }
        Qs[c * 4 + 0][qi] = qv.x;
        Qs[c * 4 + 1][qi] = qv.y;
        Qs[c * 4 + 2][qi] = qv.z;
        Qs[c * 4 + 3][qi] = qv.w;
        int kx = n0 + qi;
        float4 kv = make_float4(0.f, 0.f, 0.f, 0.f);
        if (kx < Lc)
            kv = *(const float4*)&g_kf[(bh * Lc + kx) * DIMc + c * 4];
        Ks[c * 4 + 0][qi] = kv.x;
        Ks[c * 4 + 1][qi] = kv.y;
        Ks[c * 4 + 2][qi] = kv.z;
        Ks[c * 4 + 3][qi] = kv.w;
    }
    __syncthreads();

    const int tx = tid & 15;
    const int ty = tid >> 4;
    float acc[4][4];
#pragma unroll
    for (int i = 0; i < 4; i++)
#pragma unroll
        for (int j = 0; j < 4; j++) acc[i][j] = 0.0f;

#pragma unroll
    for (int d = 0; d < 36; d++) {
        float4 av4 = *(const float4*)&Qs[d][ty * 4];
        float4 bv4 = *(const float4*)&Ks[d][tx * 4];
        float ar[4] = {av4.x, av4.y, av4.z, av4.w};
        float br[4] = {bv4.x, bv4.y, bv4.z, bv4.w};
#pragma unroll
        for (int i = 0; i < 4; i++)
#pragma unroll
            for (int j = 0; j < 4; j++) acc[i][j] += ar[i] * br[j];
    }

#pragma unroll
    for (int i = 0; i < 4; i++) {
        int q = m0 + ty * 4 + i;
        if (q >= NQc) continue;
#pragma unroll
        for (int j = 0; j < 4; j++) {
            int kx = n0 + tx * 4 + j;
            if (kx >= Lc) continue;
            g_sim[(bh * NQc + q) * Lc + kx] = acc[i][j] * (1.0f / 6.0f);
        }
    }
}

// ---------------------------------------------------------------------------
// Row softmax over 1000 keys, in place in g_sim. grid (250, 16), 256 threads.
// ---------------------------------------------------------------------------
__global__ void __launch_bounds__(256) softmax_kernel()
{
    const int bh = blockIdx.y;
    const int q  = blockIdx.x;
    float* row = &g_sim[(bh * NQc + q) * Lc];
    const int tid = threadIdx.x;
    __shared__ float red[8];
    __shared__ float s_m, s_inv;

    float mx = -3.4e38f;
    for (int j = tid; j < Lc; j += 256) mx = fmaxf(mx, row[j]);
#pragma unroll
    for (int o = 16; o; o >>= 1) mx = fmaxf(mx, __shfl_xor_sync(0xffffffffu, mx, o));
    if ((tid & 31) == 0) red[tid >> 5] = mx;
    __syncthreads();
    if (tid == 0) {
        float t = red[0];
        for (int i = 1; i < 8; i++) t = fmaxf(t, red[i]);
        s_m = t;
    }
    __syncthreads();

    float sum = 0.0f;
    for (int j = tid; j < Lc; j += 256) {
        float e = __expf(row[j] - s_m);
        row[j] = e;
        sum += e;
    }
#pragma unroll
    for (int o = 16; o; o >>= 1) sum += __shfl_xor_sync(0xffffffffu, sum, o);
    if ((tid & 31) == 0) red[tid >> 5] = sum;
    __syncthreads();
    if (tid == 0) {
        float t = 0.0f;
        for (int i = 0; i < 8; i++) t += red[i];
        s_inv = 1.0f / t;
    }
    __syncthreads();

    float inv = s_inv;
    for (int j = tid; j < Lc; j += 256) row[j] *= inv;
}

// ---------------------------------------------------------------------------
// V mean per (bh), deterministic tree reduction. grid 16, 256 threads.
// ---------------------------------------------------------------------------
__global__ void __launch_bounds__(256) vmean_kernel()
{
    const int bh  = blockIdx.x;
    const int tid = threadIdx.x;
    float acc[36];
#pragma unroll
    for (int d = 0; d < 36; d++) acc[d] = 0.0f;

    for (int l = tid; l < Lc; l += 256) {
        const float* vp = &g_vf[(bh * Lc + l) * DIMc];
#pragma unroll
        for (int d = 0; d < 36; d++) acc[d] += vp[d];
    }
#pragma unroll
    for (int d = 0; d < 36; d++) {
#pragma unroll
        for (int o = 16; o; o >>= 1) acc[d] += __shfl_xor_sync(0xffffffffu, acc[d], o);
    }
    __shared__ float sm[8][36];
    if ((tid & 31) == 0) {
        int w = tid >> 5;
#pragma unroll
        for (int d = 0; d < 36; d++) sm[w][d] = acc[d];
    }
    __syncthreads();
    if (tid < 36) {
        float t = 0.0f;
#pragma unroll
        for (int w = 0; w < 8; w++) t += sm[w][tid];
        g_vmean[bh * DIMc + tid] = t * (1.0f / (float)Lc);
    }
}

// Fill attn output with per-head mean(V)
__global__ void __launch_bounds__(256) fill_kernel()
{
    int i = blockIdx.x * 256 + threadIdx.x;
    if (i >= Bc * Lc * Dc) return;
    int d  = i % Dc;
    int bl = i / Dc;
    int b  = bl / Lc;
    int hh = d / 36;
    int dd = d - hh * 36;
    g_attn[i] = g_vmean[(b * Hc + hh) * DIMc + dd];
}

// ---------------------------------------------------------------------------
// AV GEMM: out_sel[250,36] = P[250,1000] @ V[1000,36], split-K=2 (determin.)
// grid (4 qt, 16 bh, 2 split), 144 threads, 4x4 tiles.
// ---------------------------------------------------------------------------
__global__ void __launch_bounds__(144) av_kernel()
{
    __shared__ float Ps[16][68];
    __shared__ float Vs[16][40];
    const int m0    = blockIdx.x * 64;
    const int bh    = blockIdx.y;
    const int split = blockIdx.z;
    const int tid   = threadIdx.x;
    const int tx = tid % 16;   // q quad
    const int ty = tid / 16;   // d quad (0..8)

    float acc[4][4];
#pragma unroll
    for (int i = 0; i < 4; i++)
#pragma unroll
        for (int j = 0; j < 4; j++) acc[i][j] = 0.0f;

    for (int kt = 0; kt < 32; kt++) {
        int k0 = split * 512 + kt * 16;
        for (int i = tid; i < 1024; i += 144) {
            int kk = i & 15;
            int qi = i >> 4;
            int q = m0 + qi, k = k0 + kk;
            Ps[kk][qi] = (q < NQc && k < Lc) ? g_sim[(bh * NQc + q) * Lc + k] : 0.0f;
        }
        for (int i = tid; i < 16 * 36; i += 144) {
            int d  = i % 36;
            int kk = i / 36;
            int k = k0 + kk;
            Vs[kk][d] = (k < Lc) ? g_vf[(bh * Lc + k) * DIMc + d] : 0.0f;
        }
        __syncthreads();
#pragma unroll
        for (int kk = 0; kk < 16; kk++) {
            float4 pv4 = *(const float4*)&Ps[kk][tx * 4];
            float4 vv4 = *(const float4*)&Vs[kk][ty * 4];
            float pr[4] = {pv4.x, pv4.y, pv4.z, pv4.w};
            float vr[4] = {vv4.x, vv4.y, vv4.z, vv4.w};
#pragma unroll
            for (int i = 0; i < 4; i++)
#pragma unroll
                for (int j = 0; j < 4; j++) acc[i][j] += pr[i] * vr[j];
        }
        __syncthreads();
    }

#pragma unroll
    for (int i = 0; i < 4; i++) {
        int q = m0 + tx * 4 + i;
        if (q >= NQc) continue;
#pragma unroll
        for (int j = 0; j < 4; j++) {
            int d = ty * 4 + j;
            g_av[((split * BHc + bh) * NQc + q) * DIMc + d] = acc[i][j];
        }
    }
}

// Scatter active-query outputs into g_attn (sum of split-k slabs)
__global__ void __launch_bounds__(256) scatter_kernel()
{
    int i = blockIdx.x * 256 + threadIdx.x;
    if (i >= BHc * NQc * DIMc) return;
    int d = i % DIMc;
    int t = i / DIMc;
    int q  = t % NQc;
    int bh = t / NQc;
    int l = g_idxq[bh * NQc + q];
    float val = g_av[((0 * BHc + bh) * NQc + q) * DIMc + d]
              + g_av[((1 * BHc + bh) * NQc + q) * DIMc + d];
    int b = bh >> 3;
    int h = bh & 7;
    g_attn[(b * Lc + l) * Dc + h * 36 + d] = val;
}

// ---------------------------------------------------------------------------
// LayerNorm over D=288: out = LN(a + b). WHICH 0: a=x(param), out=g_h1f.
// WHICH 1: a=g_f2f, b=g_h1f, out=param. grid 2000, 288 threads.
// ---------------------------------------------------------------------------
template <int WHICH>
__global__ void __launch_bounds__(288) ln_kernel(
    const float* __restrict__ xin, float* __restrict__ oout,
    const float* __restrict__ gg, const float* __restrict__ bb)
{
    const int r = blockIdx.x;
    const int d = threadIdx.x;
    const int base = r * Dc;

    float v;
    if (WHICH == 0) v = xin[base + d] + g_attn[base + d];
    else            v = g_f2f[base + d] + g_h1f[base + d];

    __shared__ float red[9];
    __shared__ float s_mu, s_rs;

    float s = v;
#pragma unroll
    for (int o = 16; o; o >>= 1) s += __shfl_xor_sync(0xffffffffu, s, o);
    if ((d & 31) == 0) red[d >> 5] = s;
    __syncthreads();
    if (d == 0) {
        float t = 0.0f;
        for (int i = 0; i < 9; i++) t += red[i];
        s_mu = t * (1.0f / (float)Dc);
    }
    __syncthreads();

    float dv = v - s_mu;
    float qv = dv * dv;
#pragma unroll
    for (int o = 16; o; o >>= 1) qv += __shfl_xor_sync(0xffffffffu, qv, o);
    if ((d & 31) == 0) red[d >> 5] = qv;
    __syncthreads();
    if (d == 0) {
        float t = 0.0f;
        for (int i = 0; i < 9; i++) t += red[i];
        s_rs = rsqrtf(t * (1.0f / (float)Dc) + 1e-5f);
    }
    __syncthreads();

    float outv = dv * s_rs * gg[d] + bb[d];
    if (WHICH == 0) g_h1f[base + d] = outv;
    else            oout[base + d]  = outv;
}

// ---------------------------------------------------------------------------
extern "C" void kernel_launch(void* const* d_in, const int* in_sizes, int n_in,
                              void* d_out, int out_size)
{
    (void)in_sizes; (void)n_in; (void)out_size;
    const float* x   = (const float*)d_in[0];
    const int*   ik  = (const int*)d_in[1];
    const float* Wq  = (const float*)d_in[2];
    const float* bq  = (const float*)d_in[3];
    const float* Wk  = (const float*)d_in[4];
    const float* bk  = (const float*)d_in[5];
    const float* Wv  = (const float*)d_in[6];
    const float* bv  = (const float*)d_in[7];
    const float* W1  = (const float*)d_in[8];
    const float* b1  = (const float*)d_in[9];
    const float* W2  = (const float*)d_in[10];
    const float* b2  = (const float*)d_in[11];
    const float* g1  = (const float*)d_in[12];
    const float* be1 = (const float*)d_in[13];
    const float* g2  = (const float*)d_in[14];
    const float* be2 = (const float*)d_in[15];
    float* out = (float*)d_out;

    const int measure_smem = Lc * DIMc * (int)sizeof(float);  // 144 KB
    cudaFuncSetAttribute(measure_kernel,
                         cudaFuncAttributeMaxDynamicSharedMemorySize, measure_smem);

    // 1) QKV projections (N=864, K=288): 27x16 = 432 blocks
    gemm3<0, 32><<<dim3(864 / 32, (Mrows + 127) / 128), 256>>>(
        x, Mrows, 864, Dc, Wq, Wk, Wv, bq, bk, bv);

    // 2) sparsity measure: 9x16 = 144 blocks (1 wave at 1 CTA/SM)
    measure_kernel<<<dim3(9, BHc), 256, measure_smem>>>(ik);

    // 3) top-250 active queries per (b,h)
    topk_kernel<<<BHc, 512>>>();

    // 4) sim for selected queries
    sim_kernel<<<dim3(16, 4, BHc), 256>>>();

    // 5) softmax rows
    softmax_kernel<<<dim3(NQc, BHc), 256>>>();

    // 6) mean(V) + lazy fill
    vmean_kernel<<<BHc, 256>>>();
    fill_kernel<<<(Bc * Lc * Dc + 255) / 256, 256>>>();

    // 7) attn @ V (split-k = 2), then scatter active outputs
    av_kernel<<<dim3(4, BHc, 2), 144>>>();
    scatter_kernel<<<(BHc * NQc * DIMc + 255) / 256, 256>>>();

    // 8) residual + LN1
    ln_kernel<0><<<Mrows, 288>>>(x, nullptr, g1, be1);

    // 9) FFN (exact GELU both layers): 9x16=144 blocks each
    gemm3<1, 64><<<dim3(DFFc / 64, (Mrows + 127) / 128), 256>>>(
        nullptr, Mrows, DFFc, Dc, W1, nullptr, nullptr, nullptr, b1, nullptr);
    gemm3<2, 32><<<dim3(Dc / 32, (Mrows + 127) / 128), 256>>>(
        nullptr, Mrows, Dc, DFFc, W2, nullptr, nullptr, nullptr, b2, nullptr);

    // 10) residual + LN2 -> output
    ln_kernel<1><<<Mrows, 288>>>(nullptr, out, g2, be2);
}

// round 4
// speedup vs baseline: 1.2612x; 1.0314x over previous
#include <cuda_runtime.h>
#include <math.h>

// Problem constants
constexpr int Bc   = 2;
constexpr int Lc   = 1000;
constexpr int Dc   = 288;
constexpr int Hc   = 8;
constexpr int DIMc = 36;
constexpr int DFFc = 576;
constexpr int KSc  = 250;
constexpr int NQc  = 250;
constexpr int BHc  = Bc * Hc;      // 16
constexpr int Mrows = Bc * Lc;     // 2000

// Scratch (static device globals; no allocation)
__device__ float g_qf[BHc * Lc * DIMc];
__device__ float g_kf[BHc * Lc * DIMc];
__device__ float g_vf[BHc * Lc * DIMc];
__device__ float g_measure[BHc * Lc];
__device__ int   g_idxq[BHc * NQc];
__device__ float g_sim[BHc * NQc * Lc];          // raw sim -> unnormalized exp (in place)
__device__ float g_inv[BHc * NQc];               // 1/softmax-sum per selected row
__device__ float g_av[2 * BHc * NQc * DIMc];     // split-k slabs
__device__ float g_vmean[BHc * DIMc];
__device__ float g_attn[Bc * Lc * Dc];
__device__ float g_h1f[Bc * Lc * Dc];
__device__ float g_f1f[Bc * Lc * DFFc];
__device__ float g_f2f[Bc * Lc * Dc];

__device__ __forceinline__ float gelu_exact(float x) {
    return 0.5f * x * (1.0f + erff(x * 0.7071067811865475f));
}

// ---------------------------------------------------------------------------
// Tiled GEMM with 2-stage smem double buffering (1 sync per k-tile):
// C[M,N] = A[M,K] @ W^T (+bias, epilogue per MODE)
// MODE 0: QKV (N=864 : Wq|Wk|Wv), scatter to g_qf/g_kf/g_vf in [bh][l][d]
// MODE 1: FFN1: A=g_h1f, gelu -> g_f1f
// MODE 2: FFN2: A=g_f1f, gelu -> g_f2f
// BM=128, BN in {32,64,96}, BK=16, 256 threads, 8 x (BN/16) outputs/thread.
// ---------------------------------------------------------------------------
template <int MODE, int BN>
__global__ void __launch_bounds__(256) gemm4(
    const float* __restrict__ A_in, int M, int N, int K,
    const float* __restrict__ W0, const float* __restrict__ W1p,
    const float* __restrict__ W2p,
    const float* __restrict__ b0, const float* __restrict__ b1p,
    const float* __restrict__ b2p)
{
    constexpr int TN   = BN / 16;       // cols per thread (2/4/6)
    constexpr int BSTR = BN + 4;        // padded B row stride
    constexpr int NB   = BN / 16;       // B elements loaded per thread

    const float* A = (MODE == 0) ? A_in : (MODE == 1 ? g_h1f : g_f1f);

    __shared__ __align__(16) float As[2][16][132];
    __shared__ __align__(16) float Bs[2][16][BSTR];

    const int m0 = blockIdx.y * 128;
    const int n0 = blockIdx.x * BN;
    const int tid = threadIdx.x;
    const int tx = tid & 15;    // column group
    const int ty = tid >> 4;    // row group (8 rows each)

    float acc[8][TN];
#pragma unroll
    for (int i = 0; i < 8; i++)
#pragma unroll
        for (int j = 0; j < TN; j++) acc[i][j] = 0.0f;

    float a_r[8], b_r[NB];

    auto load_tile = [&](int kt) {
        const int k0 = kt * 16;
#pragma unroll
        for (int p = 0; p < 8; p++) {
            int i  = tid + p * 256;
            int kk = i & 15;
            int mi = i >> 4;
            int r  = m0 + mi;
            a_r[p] = (r < M) ? A[r * K + k0 + kk] : 0.0f;
        }
#pragma unroll
        for (int p = 0; p < NB; p++) {
            int i  = tid + p * 256;
            int kk = i & 15;
            int nc = i >> 4;
            int col = n0 + nc;
            float wv;
            if (MODE == 0) {
                const float* w; int cc;
                if (col < 288)      { w = W0;  cc = col; }
                else if (col < 576) { w = W1p; cc = col - 288; }
                else                { w = W2p; cc = col - 576; }
                wv = w[cc * K + k0 + kk];
            } else {
                wv = W0[col * K + k0 + kk];
            }
            b_r[p] = wv;
        }
    };
    auto store_tile = [&](int buf) {
#pragma unroll
        for (int p = 0; p < 8; p++) {
            int i  = tid + p * 256;
            As[buf][i & 15][i >> 4] = a_r[p];
        }
#pragma unroll
        for (int p = 0; p < NB; p++) {
            int i  = tid + p * 256;
            Bs[buf][i & 15][i >> 4] = b_r[p];
        }
    };

    const int ktiles = K / 16;
    load_tile(0);
    store_tile(0);
    __syncthreads();

    for (int kt = 0; kt < ktiles; kt++) {
        const int cur = kt & 1;
        if (kt + 1 < ktiles) load_tile(kt + 1);

#pragma unroll
        for (int kk = 0; kk < 16; kk++) {
            float a8[8];
            float4 a0 = *(const float4*)&As[cur][kk][ty * 8];
            float4 a1 = *(const float4*)&As[cur][kk][ty * 8 + 4];
            a8[0] = a0.x; a8[1] = a0.y; a8[2] = a0.z; a8[3] = a0.w;
            a8[4] = a1.x; a8[5] = a1.y; a8[6] = a1.z; a8[7] = a1.w;
            float bv[TN];
            if (TN == 6) {
#pragma unroll
                for (int c = 0; c < 3; c++) {
                    float2 b2v = *(const float2*)&Bs[cur][kk][tx * 6 + 2 * c];
                    bv[2 * c] = b2v.x; bv[2 * c + 1] = b2v.y;
                }
            } else if (TN == 4) {
                float4 b4 = *(const float4*)&Bs[cur][kk][tx * 4];
                bv[0] = b4.x; bv[1] = b4.y; bv[2] = b4.z; bv[3] = b4.w;
            } else {
                float2 b2v = *(const float2*)&Bs[cur][kk][tx * 2];
                bv[0] = b2v.x; bv[1] = b2v.y;
            }
#pragma unroll
            for (int i = 0; i < 8; i++)
#pragma unroll
                for (int j = 0; j < TN; j++) acc[i][j] += a8[i] * bv[j];
        }

        if (kt + 1 < ktiles) store_tile((kt + 1) & 1);
        __syncthreads();
    }

    // epilogue
#pragma unroll
    for (int i = 0; i < 8; i++) {
        int r = m0 + ty * 8 + i;
        if (r >= M) continue;
#pragma unroll
        for (int j = 0; j < TN; j++) {
            int col = n0 + tx * TN + j;
            float v = acc[i][j];
            if (MODE == 0) {
                int cc; const float* bias; float* dst;
                if (col < 288)      { cc = col;       bias = b0;  dst = g_qf; }
                else if (col < 576) { cc = col - 288; bias = b1p; dst = g_kf; }
                else                { cc = col - 576; bias = b2p; dst = g_vf; }
                v += bias[cc];
                int h  = cc / 36;
                int dd = cc - h * 36;
                int bb = r / Lc;
                int ll = r - bb * Lc;
                dst[((bb * Hc + h) * Lc + ll) * DIMc + dd] = v;
            } else {
                v = gelu_exact(v + b1p[col]);
                if (MODE == 1) g_f1f[r * N + col] = v;
                else           g_f2f[r * N + col] = v;
            }
        }
    }
}

// ---------------------------------------------------------------------------
// Measure kernel: measure[bh][l] = max_j q.k[idx] - sum_j(q.k[idx]) / L
// K[bh] staged in dynamic smem natural layout (144B rows, float4 aligned).
// grid (9 chunks, 16 bh) = 144 blocks. 256 threads, warp-per-query.
// ---------------------------------------------------------------------------
__global__ void __launch_bounds__(256) measure_kernel(const int* __restrict__ ik)
{
    extern __shared__ __align__(16) float ks[];   // [Lc][36]
    const int chunk = blockIdx.x;
    const int bh    = blockIdx.y;
    const int tid   = threadIdx.x;

    const float4* ksrc4 = (const float4*)&g_kf[bh * Lc * DIMc];
    float4* kdst4 = (float4*)ks;
    for (int i = tid; i < Lc * DIMc / 4; i += 256) kdst4[i] = ksrc4[i];
    __syncthreads();

    const int warp = tid >> 5;
    const int lane = tid & 31;
    const int lstart = chunk * 112;
    const int lend   = min(lstart + 112, Lc);

    for (int l = lstart + warp; l < lend; l += 8) {
        float4 q4[9];
        const float4* qp = (const float4*)&g_qf[(bh * Lc + l) * DIMc];
#pragma unroll
        for (int c = 0; c < 9; c++) q4[c] = qp[c];

        float mx = -3.4e38f;
        float sm = 0.0f;
#pragma unroll
        for (int jj = 0; jj < 8; jj++) {
            int j = lane + jj * 32;
            if (j < KSc) {
                int idx = ik[l * KSc + j];
                const float4* kp = (const float4*)&ks[idx * DIMc];
                float accd = 0.0f;
#pragma unroll
                for (int c = 0; c < 9; c++) {
                    float4 kv = kp[c];
                    accd += q4[c].x * kv.x + q4[c].y * kv.y
                          + q4[c].z * kv.z + q4[c].w * kv.w;
                }
                mx = fmaxf(mx, accd);
                sm += accd;
            }
        }
#pragma unroll
        for (int o = 16; o; o >>= 1) {
            mx = fmaxf(mx, __shfl_xor_sync(0xffffffffu, mx, o));
            sm += __shfl_xor_sync(0xffffffffu, sm, o);
        }
        if (lane == 0) g_measure[bh * Lc + l] = mx - sm * (1.0f / (float)Lc);
    }
}

// ---------------------------------------------------------------------------
// TopK: per bh, top-250 of 1000 measures via bitonic sort of packed u64 keys.
// ---------------------------------------------------------------------------
__global__ void __launch_bounds__(512) topk_kernel()
{
    __shared__ unsigned long long keys[1024];
    const int bh  = blockIdx.x;
    const int tid = threadIdx.x;

    for (int i = tid; i < 1024; i += 512) {
        unsigned long long kv = 0ULL;
        if (i < Lc) {
            float f = g_measure[bh * Lc + i];
            unsigned u = __float_as_uint(f);
            u = (u & 0x80000000u) ? ~u : (u | 0x80000000u);
            kv = ((unsigned long long)u << 32) | (unsigned)(~i);
        }
        keys[i] = kv;
    }
    __syncthreads();

    for (int k = 2; k <= 1024; k <<= 1) {
        for (int j = k >> 1; j > 0; j >>= 1) {
#pragma unroll
            for (int w = 0; w < 2; w++) {
                int i   = tid + w * 512;
                int ixj = i ^ j;
                if (ixj > i) {
                    bool descend = ((i & k) == 0);
                    unsigned long long a = keys[i];
                    unsigned long long b = keys[ixj];
                    bool sw = descend ? (a < b) : (a > b);
                    if (sw) { keys[i] = b; keys[ixj] = a; }
                }
            }
            __syncthreads();
        }
    }

    if (tid < NQc) {
        unsigned low = (unsigned)keys[tid];
        g_idxq[bh * NQc + tid] = (int)(~low);
    }
}

// ---------------------------------------------------------------------------
// Selected-query sim GEMM: sim[bh][q][k] = (1/6) * q_sel . k
// block: 64 queries x 128 keys. grid (8 kt, 4 qt, 16 bh) = 512 blocks.
// 256 threads, 4x8 outputs per thread.
// ---------------------------------------------------------------------------
__global__ void __launch_bounds__(256) sim_kernel()
{
    __shared__ float Qs[36][68];
    __shared__ float Ks[36][132];
    __shared__ int   qidx[64];
    const int bh = blockIdx.z;
    const int n0 = blockIdx.x * 128;
    const int m0 = blockIdx.y * 64;
    const int tid = threadIdx.x;

    if (tid < 64) {
        int q = m0 + tid;
        qidx[tid] = (q < NQc) ? g_idxq[bh * NQc + q] : 0;
    }
    __syncthreads();

    // Q: 64 rows x 9 float4
    for (int i = tid; i < 576; i += 256) {
        int qi = i / 9;
        int c  = i - qi * 9;
        int q = m0 + qi;
        float4 qv = make_float4(0.f, 0.f, 0.f, 0.f);
        if (q < NQc) {
            int row = qidx[qi];
            qv = *(const float4*)&g_qf[(bh * Lc + row) * DIMc + c * 4];
        }
        Qs[c * 4 + 0][qi] = qv.x;
        Qs[c * 4 + 1][qi] = qv.y;
        Qs[c * 4 + 2][qi] = qv.z;
        Qs[c * 4 + 3][qi] = qv.w;
    }
    // K: 128 rows x 9 float4
    for (int i = tid; i < 1152; i += 256) {
        int ki = i / 9;
        int c  = i - ki * 9;
        int kx = n0 + ki;
        float4 kv = make_float4(0.f, 0.f, 0.f, 0.f);
        if (kx < Lc)
            kv = *(const float4*)&g_kf[(bh * Lc + kx) * DIMc + c * 4];
        Ks[c * 4 + 0][ki] = kv.x;
        Ks[c * 4 + 1][ki] = kv.y;
        Ks[c * 4 + 2][ki] = kv.z;
        Ks[c * 4 + 3][ki] = kv.w;
    }
    __syncthreads();

    const int tx = tid & 15;   // key octet
    const int ty = tid >> 4;   // query quad
    float acc[4][8];
#pragma unroll
    for (int i = 0; i < 4; i++)
#pragma unroll
        for (int j = 0; j < 8; j++) acc[i][j] = 0.0f;

#pragma unroll
    for (int d = 0; d < 36; d++) {
        float4 av4 = *(const float4*)&Qs[d][ty * 4];
        float4 b0 = *(const float4*)&Ks[d][tx * 8];
        float4 b1 = *(const float4*)&Ks[d][tx * 8 + 4];
        float ar[4] = {av4.x, av4.y, av4.z, av4.w};
        float br[8] = {b0.x, b0.y, b0.z, b0.w, b1.x, b1.y, b1.z, b1.w};
#pragma unroll
        for (int i = 0; i < 4; i++)
#pragma unroll
            for (int j = 0; j < 8; j++) acc[i][j] += ar[i] * br[j];
    }

#pragma unroll
    for (int i = 0; i < 4; i++) {
        int q = m0 + ty * 4 + i;
        if (q >= NQc) continue;
#pragma unroll
        for (int j = 0; j < 8; j++) {
            int kx = n0 + tx * 8 + j;
            if (kx >= Lc) continue;
            g_sim[(bh * NQc + q) * Lc + kx] = acc[i][j] * (1.0f / 6.0f);
        }
    }
}

// ---------------------------------------------------------------------------
// Row softmax (unnormalized): store exp(s - max) in place, 1/sum in g_inv.
// grid (250, 16), 256 threads.
// ---------------------------------------------------------------------------
__global__ void __launch_bounds__(256) softmax_kernel()
{
    const int bh = blockIdx.y;
    const int q  = blockIdx.x;
    float* row = &g_sim[(bh * NQc + q) * Lc];
    const int tid = threadIdx.x;
    __shared__ float red[8];
    __shared__ float s_m;

    float mx = -3.4e38f;
    for (int j = tid; j < Lc; j += 256) mx = fmaxf(mx, row[j]);
#pragma unroll
    for (int o = 16; o; o >>= 1) mx = fmaxf(mx, __shfl_xor_sync(0xffffffffu, mx, o));
    if ((tid & 31) == 0) red[tid >> 5] = mx;
    __syncthreads();
    if (tid == 0) {
        float t = red[0];
        for (int i = 1; i < 8; i++) t = fmaxf(t, red[i]);
        s_m = t;
    }
    __syncthreads();

    float sum = 0.0f;
    for (int j = tid; j < Lc; j += 256) {
        float e = __expf(row[j] - s_m);
        row[j] = e;
        sum += e;
    }
#pragma unroll
    for (int o = 16; o; o >>= 1) sum += __shfl_xor_sync(0xffffffffu, sum, o);
    if ((tid & 31) == 0) red[tid >> 5] = sum;
    __syncthreads();
    if (tid == 0) {
        float t = 0.0f;
        for (int i = 0; i < 8; i++) t += red[i];
        g_inv[bh * NQc + q] = 1.0f / t;
    }
}

// ---------------------------------------------------------------------------
// V mean per (bh), deterministic tree reduction. grid 16, 256 threads.
// ---------------------------------------------------------------------------
__global__ void __launch_bounds__(256) vmean_kernel()
{
    const int bh  = blockIdx.x;
    const int tid = threadIdx.x;
    float acc[36];
#pragma unroll
    for (int d = 0; d < 36; d++) acc[d] = 0.0f;

    for (int l = tid; l < Lc; l += 256) {
        const float* vp = &g_vf[(bh * Lc + l) * DIMc];
#pragma unroll
        for (int d = 0; d < 36; d++) acc[d] += vp[d];
    }
#pragma unroll
    for (int d = 0; d < 36; d++) {
#pragma unroll
        for (int o = 16; o; o >>= 1) acc[d] += __shfl_xor_sync(0xffffffffu, acc[d], o);
    }
    __shared__ float sm[8][36];
    if ((tid & 31) == 0) {
        int w = tid >> 5;
#pragma unroll
        for (int d = 0; d < 36; d++) sm[w][d] = acc[d];
    }
    __syncthreads();
    if (tid < 36) {
        float t = 0.0f;
#pragma unroll
        for (int w = 0; w < 8; w++) t += sm[w][tid];
        g_vmean[bh * DIMc + tid] = t * (1.0f / (float)Lc);
    }
}

// Fill attn output with per-head mean(V)
__global__ void __launch_bounds__(256) fill_kernel()
{
    int i = blockIdx.x * 256 + threadIdx.x;
    if (i >= Bc * Lc * Dc) return;
    int d  = i % Dc;
    int bl = i / Dc;
    int b  = bl / Lc;
    int hh = d / 36;
    int dd = d - hh * 36;
    g_attn[i] = g_vmean[(b * Hc + hh) * DIMc + dd];
}

// ---------------------------------------------------------------------------
// AV GEMM: out_sel[250,36] = E[250,1000] @ V[1000,36], split-K=2 (determin.)
// E is the unnormalized exp; scaling by 1/sum happens in scatter.
// grid (4 qt, 16 bh, 2 split), 144 threads, 4x4 tiles.
// ---------------------------------------------------------------------------
__global__ void __launch_bounds__(144) av_kernel()
{
    __shared__ float Ps[16][68];
    __shared__ float Vs[16][40];
    const int m0    = blockIdx.x * 64;
    const int bh    = blockIdx.y;
    const int split = blockIdx.z;
    const int tid   = threadIdx.x;
    const int tx = tid % 16;   // q quad
    const int ty = tid / 16;   // d quad (0..8)

    float acc[4][4];
#pragma unroll
    for (int i = 0; i < 4; i++)
#pragma unroll
        for (int j = 0; j < 4; j++) acc[i][j] = 0.0f;

    for (int kt = 0; kt < 32; kt++) {
        int k0 = split * 512 + kt * 16;
        for (int i = tid; i < 1024; i += 144) {
            int kk = i & 15;
            int qi = i >> 4;
            int q = m0 + qi, k = k0 + kk;
            Ps[kk][qi] = (q < NQc && k < Lc) ? g_sim[(bh * NQc + q) * Lc + k] : 0.0f;
        }
        for (int i = tid; i < 16 * 36; i += 144) {
            int d  = i % 36;
            int kk = i / 36;
            int k = k0 + kk;
            Vs[kk][d] = (k < Lc) ? g_vf[(bh * Lc + k) * DIMc + d] : 0.0f;
        }
        __syncthreads();
#pragma unroll
        for (int kk = 0; kk < 16; kk++) {
            float4 pv4 = *(const float4*)&Ps[kk][tx * 4];
            float4 vv4 = *(const float4*)&Vs[kk][ty * 4];
            float pr[4] = {pv4.x, pv4.y, pv4.z, pv4.w};
            float vr[4] = {vv4.x, vv4.y, vv4.z, vv4.w};
#pragma unroll
            for (int i = 0; i < 4; i++)
#pragma unroll
                for (int j = 0; j < 4; j++) acc[i][j] += pr[i] * vr[j];
        }
        __syncthreads();
    }

#pragma unroll
    for (int i = 0; i < 4; i++) {
        int q = m0 + tx * 4 + i;
        if (q >= NQc) continue;
#pragma unroll
        for (int j = 0; j < 4; j++) {
            int d = ty * 4 + j;
            g_av[((split * BHc + bh) * NQc + q) * DIMc + d] = acc[i][j];
        }
    }
}

// Scatter active-query outputs into g_attn (sum of split-k slabs, scaled)
__global__ void __launch_bounds__(256) scatter_kernel()
{
    int i = blockIdx.x * 256 + threadIdx.x;
    if (i >= BHc * NQc * DIMc) return;
    int d = i % DIMc;
    int t = i / DIMc;
    int q  = t % NQc;
    int bh = t / NQc;
    int l = g_idxq[bh * NQc + q];
    float val = (g_av[((0 * BHc + bh) * NQc + q) * DIMc + d]
               + g_av[((1 * BHc + bh) * NQc + q) * DIMc + d]) * g_inv[bh * NQc + q];
    int b = bh >> 3;
    int h = bh & 7;
    g_attn[(b * Lc + l) * Dc + h * 36 + d] = val;
}

// ---------------------------------------------------------------------------
// LayerNorm over D=288: out = LN(a + b). WHICH 0: a=x(param), out=g_h1f.
// WHICH 1: a=g_f2f, b=g_h1f, out=param. grid 2000, 288 threads.
// ---------------------------------------------------------------------------
template <int WHICH>
__global__ void __launch_bounds__(288) ln_kernel(
    const float* __restrict__ xin, float* __restrict__ oout,
    const float* __restrict__ gg, const float* __restrict__ bb)
{
    const int r = blockIdx.x;
    const int d = threadIdx.x;
    const int base = r * Dc;

    float v;
    if (WHICH == 0) v = xin[base + d] + g_attn[base + d];
    else            v = g_f2f[base + d] + g_h1f[base + d];

    __shared__ float red[9];
    __shared__ float s_mu, s_rs;

    float s = v;
#pragma unroll
    for (int o = 16; o; o >>= 1) s += __shfl_xor_sync(0xffffffffu, s, o);
    if ((d & 31) == 0) red[d >> 5] = s;
    __syncthreads();
    if (d == 0) {
        float t = 0.0f;
        for (int i = 0; i < 9; i++) t += red[i];
        s_mu = t * (1.0f / (float)Dc);
    }
    __syncthreads();

    float dv = v - s_mu;
    float qv = dv * dv;
#pragma unroll
    for (int o = 16; o; o >>= 1) qv += __shfl_xor_sync(0xffffffffu, qv, o);
    if ((d & 31) == 0) red[d >> 5] = qv;
    __syncthreads();
    if (d == 0) {
        float t = 0.0f;
        for (int i = 0; i < 9; i++) t += red[i];
        s_rs = rsqrtf(t * (1.0f / (float)Dc) + 1e-5f);
    }
    __syncthreads();

    float outv = dv * s_rs * gg[d] + bb[d];
    if (WHICH == 0) g_h1f[base + d] = outv;
    else            oout[base + d]  = outv;
}

// ---------------------------------------------------------------------------
extern "C" void kernel_launch(void* const* d_in, const int* in_sizes, int n_in,
                              void* d_out, int out_size)
{
    (void)in_sizes; (void)n_in; (void)out_size;
    const float* x   = (const float*)d_in[0];
    const int*   ik  = (const int*)d_in[1];
    const float* Wq  = (const float*)d_in[2];
    const float* bq  = (const float*)d_in[3];
    const float* Wk  = (const float*)d_in[4];
    const float* bk  = (const float*)d_in[5];
    const float* Wv  = (const float*)d_in[6];
    const float* bv  = (const float*)d_in[7];
    const float* W1  = (const float*)d_in[8];
    const float* b1  = (const float*)d_in[9];
    const float* W2  = (const float*)d_in[10];
    const float* b2  = (const float*)d_in[11];
    const float* g1  = (const float*)d_in[12];
    const float* be1 = (const float*)d_in[13];
    const float* g2  = (const float*)d_in[14];
    const float* be2 = (const float*)d_in[15];
    float* out = (float*)d_out;

    const int measure_smem = Lc * DIMc * (int)sizeof(float);  // 144 KB
    cudaFuncSetAttribute(measure_kernel,
                         cudaFuncAttributeMaxDynamicSharedMemorySize, measure_smem);

    // 1) QKV projections (N=864, K=288): 9x16 = 144 blocks = 1 wave
    gemm4<0, 96><<<dim3(864 / 96, (Mrows + 127) / 128), 256>>>(
        x, Mrows, 864, Dc, Wq, Wk, Wv, bq, bk, bv);

    // 2) sparsity measure: 9x16 = 144 blocks
    measure_kernel<<<dim3(9, BHc), 256, measure_smem>>>(ik);

    // 3) top-250 active queries per (b,h)
    topk_kernel<<<BHc, 512>>>();

    // 4) sim for selected queries: (8,4,16) = 512 blocks
    sim_kernel<<<dim3(8, 4, BHc), 256>>>();

    // 5) softmax rows (unnormalized exp + inverse sums)
    softmax_kernel<<<dim3(NQc, BHc), 256>>>();

    // 6) mean(V) + lazy fill
    vmean_kernel<<<BHc, 256>>>();
    fill_kernel<<<(Bc * Lc * Dc + 255) / 256, 256>>>();

    // 7) attn @ V (split-k = 2), then scatter active outputs (with 1/sum)
    av_kernel<<<dim3(4, BHc, 2), 144>>>();
    scatter_kernel<<<(BHc * NQc * DIMc + 255) / 256, 256>>>();

    // 8) residual + LN1
    ln_kernel<0><<<Mrows, 288>>>(x, nullptr, g1, be1);

    // 9) FFN (exact GELU both layers): 9x16 = 144 blocks each
    gemm4<1, 64><<<dim3(DFFc / 64, (Mrows + 127) / 128), 256>>>(
        nullptr, Mrows, DFFc, Dc, W1, nullptr, nullptr, nullptr, b1, nullptr);
    gemm4<2, 32><<<dim3(Dc / 32, (Mrows + 127) / 128), 256>>>(
        nullptr, Mrows, Dc, DFFc, W2, nullptr, nullptr, nullptr, b2, nullptr);

    // 10) residual + LN2 -> output
    ln_kernel<1><<<Mrows, 288>>>(nullptr, out, g2, be2);
}

// round 5
// speedup vs baseline: 1.6549x; 1.3121x over previous
#include <cuda_runtime.h>
#include <math.h>

// Problem constants
constexpr int Bc   = 2;
constexpr int Lc   = 1000;
constexpr int Dc   = 288;
constexpr int Hc   = 8;
constexpr int DIMc = 36;
constexpr int DFFc = 576;
constexpr int KSc  = 250;
constexpr int NQc  = 250;
constexpr int BHc  = Bc * Hc;      // 16
constexpr int Mrows = Bc * Lc;     // 2000

// Scratch (static device globals; no allocation)
__device__ float g_qf[BHc * Lc * DIMc];
__device__ float g_kf[BHc * Lc * DIMc];
__device__ float g_vf[BHc * Lc * DIMc];
__device__ float g_measure[BHc * Lc];
__device__ int   g_idxq[BHc * NQc];
__device__ float g_vmean[BHc * DIMc];
__device__ float g_attn[Bc * Lc * Dc];
__device__ float g_h1f[Bc * Lc * Dc];
__device__ float g_f1f[Bc * Lc * DFFc];
__device__ float g_f2f[Bc * Lc * Dc];

__device__ __forceinline__ float gelu_exact(float x) {
    return 0.5f * x * (1.0f + erff(x * 0.7071067811865475f));
}

// ---------------------------------------------------------------------------
// Tiled GEMM with 2-stage smem double buffering (1 sync per k-tile):
// C[M,N] = A[M,K] @ W^T (+bias, epilogue per MODE)
// MODE 0: QKV (N=864 : Wq|Wk|Wv), scatter to g_qf/g_kf/g_vf in [bh][l][d]
// MODE 1: FFN1: A=g_h1f, gelu -> g_f1f
// MODE 2: FFN2: A=g_f1f, gelu -> g_f2f
// ---------------------------------------------------------------------------
template <int MODE, int BN>
__global__ void __launch_bounds__(256) gemm4(
    const float* __restrict__ A_in, int M, int N, int K,
    const float* __restrict__ W0, const float* __restrict__ W1p,
    const float* __restrict__ W2p,
    const float* __restrict__ b0, const float* __restrict__ b1p,
    const float* __restrict__ b2p)
{
    constexpr int TN   = BN / 16;
    constexpr int BSTR = BN + 4;
    constexpr int NB   = BN / 16;

    const float* A = (MODE == 0) ? A_in : (MODE == 1 ? g_h1f : g_f1f);

    __shared__ __align__(16) float As[2][16][132];
    __shared__ __align__(16) float Bs[2][16][BSTR];

    const int m0 = blockIdx.y * 128;
    const int n0 = blockIdx.x * BN;
    const int tid = threadIdx.x;
    const int tx = tid & 15;
    const int ty = tid >> 4;

    float acc[8][TN];
#pragma unroll
    for (int i = 0; i < 8; i++)
#pragma unroll
        for (int j = 0; j < TN; j++) acc[i][j] = 0.0f;

    float a_r[8], b_r[NB];

    auto load_tile = [&](int kt) {
        const int k0 = kt * 16;
#pragma unroll
        for (int p = 0; p < 8; p++) {
            int i  = tid + p * 256;
            int kk = i & 15;
            int mi = i >> 4;
            int r  = m0 + mi;
            a_r[p] = (r < M) ? A[r * K + k0 + kk] : 0.0f;
        }
#pragma unroll
        for (int p = 0; p < NB; p++) {
            int i  = tid + p * 256;
            int kk = i & 15;
            int nc = i >> 4;
            int col = n0 + nc;
            float wv;
            if (MODE == 0) {
                const float* w; int cc;
                if (col < 288)      { w = W0;  cc = col; }
                else if (col < 576) { w = W1p; cc = col - 288; }
                else                { w = W2p; cc = col - 576; }
                wv = w[cc * K + k0 + kk];
            } else {
                wv = W0[col * K + k0 + kk];
            }
            b_r[p] = wv;
        }
    };
    auto store_tile = [&](int buf) {
#pragma unroll
        for (int p = 0; p < 8; p++) {
            int i  = tid + p * 256;
            As[buf][i & 15][i >> 4] = a_r[p];
        }
#pragma unroll
        for (int p = 0; p < NB; p++) {
            int i  = tid + p * 256;
            Bs[buf][i & 15][i >> 4] = b_r[p];
        }
    };

    const int ktiles = K / 16;
    load_tile(0);
    store_tile(0);
    __syncthreads();

    for (int kt = 0; kt < ktiles; kt++) {
        const int cur = kt & 1;
        if (kt + 1 < ktiles) load_tile(kt + 1);

#pragma unroll
        for (int kk = 0; kk < 16; kk++) {
            float a8[8];
            float4 a0 = *(const float4*)&As[cur][kk][ty * 8];
            float4 a1 = *(const float4*)&As[cur][kk][ty * 8 + 4];
            a8[0] = a0.x; a8[1] = a0.y; a8[2] = a0.z; a8[3] = a0.w;
            a8[4] = a1.x; a8[5] = a1.y; a8[6] = a1.z; a8[7] = a1.w;
            float bv[TN];
            if (TN == 6) {
#pragma unroll
                for (int c = 0; c < 3; c++) {
                    float2 b2v = *(const float2*)&Bs[cur][kk][tx * 6 + 2 * c];
                    bv[2 * c] = b2v.x; bv[2 * c + 1] = b2v.y;
                }
            } else if (TN == 4) {
                float4 b4 = *(const float4*)&Bs[cur][kk][tx * 4];
                bv[0] = b4.x; bv[1] = b4.y; bv[2] = b4.z; bv[3] = b4.w;
            } else {
                float2 b2v = *(const float2*)&Bs[cur][kk][tx * 2];
                bv[0] = b2v.x; bv[1] = b2v.y;
            }
#pragma unroll
            for (int i = 0; i < 8; i++)
#pragma unroll
                for (int j = 0; j < TN; j++) acc[i][j] += a8[i] * bv[j];
        }

        if (kt + 1 < ktiles) store_tile((kt + 1) & 1);
        __syncthreads();
    }

#pragma unroll
    for (int i = 0; i < 8; i++) {
        int r = m0 + ty * 8 + i;
        if (r >= M) continue;
#pragma unroll
        for (int j = 0; j < TN; j++) {
            int col = n0 + tx * TN + j;
            float v = acc[i][j];
            if (MODE == 0) {
                int cc; const float* bias; float* dst;
                if (col < 288)      { cc = col;       bias = b0;  dst = g_qf; }
                else if (col < 576) { cc = col - 288; bias = b1p; dst = g_kf; }
                else                { cc = col - 576; bias = b2p; dst = g_vf; }
                v += bias[cc];
                int h  = cc / 36;
                int dd = cc - h * 36;
                int bb = r / Lc;
                int ll = r - bb * Lc;
                dst[((bb * Hc + h) * Lc + ll) * DIMc + dd] = v;
            } else {
                v = gelu_exact(v + b1p[col]);
                if (MODE == 1) g_f1f[r * N + col] = v;
                else           g_f2f[r * N + col] = v;
            }
        }
    }
}

// ---------------------------------------------------------------------------
// Measure kernel (unchanged from R3 best).
// ---------------------------------------------------------------------------
__global__ void __launch_bounds__(256) measure_kernel(const int* __restrict__ ik)
{
    extern __shared__ __align__(16) float ks[];   // [Lc][36]
    const int chunk = blockIdx.x;
    const int bh    = blockIdx.y;
    const int tid   = threadIdx.x;

    const float4* ksrc4 = (const float4*)&g_kf[bh * Lc * DIMc];
    float4* kdst4 = (float4*)ks;
    for (int i = tid; i < Lc * DIMc / 4; i += 256) kdst4[i] = ksrc4[i];
    __syncthreads();

    const int warp = tid >> 5;
    const int lane = tid & 31;
    const int lstart = chunk * 112;
    const int lend   = min(lstart + 112, Lc);

    for (int l = lstart + warp; l < lend; l += 8) {
        float4 q4[9];
        const float4* qp = (const float4*)&g_qf[(bh * Lc + l) * DIMc];
#pragma unroll
        for (int c = 0; c < 9; c++) q4[c] = qp[c];

        float mx = -3.4e38f;
        float sm = 0.0f;
#pragma unroll
        for (int jj = 0; jj < 8; jj++) {
            int j = lane + jj * 32;
            if (j < KSc) {
                int idx = ik[l * KSc + j];
                const float4* kp = (const float4*)&ks[idx * DIMc];
                float accd = 0.0f;
#pragma unroll
                for (int c = 0; c < 9; c++) {
                    float4 kv = kp[c];
                    accd += q4[c].x * kv.x + q4[c].y * kv.y
                          + q4[c].z * kv.z + q4[c].w * kv.w;
                }
                mx = fmaxf(mx, accd);
                sm += accd;
            }
        }
#pragma unroll
        for (int o = 16; o; o >>= 1) {
            mx = fmaxf(mx, __shfl_xor_sync(0xffffffffu, mx, o));
            sm += __shfl_xor_sync(0xffffffffu, sm, o);
        }
        if (lane == 0) g_measure[bh * Lc + l] = mx - sm * (1.0f / (float)Lc);
    }
}

// ---------------------------------------------------------------------------
// TopK (unchanged): bitonic sort of packed u64 keys, exact top_k semantics.
// ---------------------------------------------------------------------------
__global__ void __launch_bounds__(512) topk_kernel()
{
    __shared__ unsigned long long keys[1024];
    const int bh  = blockIdx.x;
    const int tid = threadIdx.x;

    for (int i = tid; i < 1024; i += 512) {
        unsigned long long kv = 0ULL;
        if (i < Lc) {
            float f = g_measure[bh * Lc + i];
            unsigned u = __float_as_uint(f);
            u = (u & 0x80000000u) ? ~u : (u | 0x80000000u);
            kv = ((unsigned long long)u << 32) | (unsigned)(~i);
        }
        keys[i] = kv;
    }
    __syncthreads();

    for (int k = 2; k <= 1024; k <<= 1) {
        for (int j = k >> 1; j > 0; j >>= 1) {
#pragma unroll
            for (int w = 0; w < 2; w++) {
                int i   = tid + w * 512;
                int ixj = i ^ j;
                if (ixj > i) {
                    bool descend = ((i & k) == 0);
                    unsigned long long a = keys[i];
                    unsigned long long b = keys[ixj];
                    bool sw = descend ? (a < b) : (a > b);
                    if (sw) { keys[i] = b; keys[ixj] = a; }
                }
            }
            __syncthreads();
        }
    }

    if (tid < NQc) {
        unsigned low = (unsigned)keys[tid];
        g_idxq[bh * NQc + tid] = (int)(~low);
    }
}

// ---------------------------------------------------------------------------
// Fused attention: per block, 32 selected queries x all 1000 keys.
// Online softmax (flash-style), direct scatter into g_attn with 1/l scale.
// Grid (8 qtiles, 16 bh) = 128 blocks, 256 threads.
// S-phase: thread = (q-pair ty, key-oct tx); PV-phase: (q-pair ty, d-triple tx<12).
// ---------------------------------------------------------------------------
constexpr int FQT  = 32;
constexpr int FKT  = 128;
constexpr int QSTR = 34;
constexpr int KSTR = 132;
constexpr int VSTR = 48;
constexpr int PSTR = 34;
constexpr int FATTN_SMEM =
    (36 * QSTR + 36 * KSTR + FKT * VSTR + FKT * PSTR) * (int)sizeof(float) + 256;

__global__ void __launch_bounds__(256) fattn_kernel()
{
    extern __shared__ __align__(16) float smem[];
    float* Qs = smem;                        // [36][QSTR]
    float* Ks = Qs + 36 * QSTR;              // [36][KSTR]
    float* Vs = Ks + 36 * KSTR;              // [FKT][VSTR]
    float* Ps = Vs + FKT * VSTR;             // [FKT][PSTR]
    int*   qrow = (int*)(Ps + FKT * PSTR);   // [FQT]

    const int bh = blockIdx.y;
    const int q0 = blockIdx.x * FQT;
    const int tid = threadIdx.x;
    const int tx = tid & 15;
    const int ty = tid >> 4;

    if (tid < FQT) {
        int q = q0 + tid;
        qrow[tid] = g_idxq[bh * NQc + (q < NQc ? q : 0)];
    }
    // zero V pad columns 36..47 (stays zero; rows only overwrite cols <36)
    for (int i = tid; i < FKT * 3; i += 256) {
        int r = i / 3, c = 36 + (i % 3) * 4;
        *(float4*)&Vs[r * VSTR + c] = make_float4(0.f, 0.f, 0.f, 0.f);
    }
    __syncthreads();

    // stage Q transposed, pre-scaled by 1/sqrt(36)
    for (int i = tid; i < FQT * 9; i += 256) {
        int qi = i / 9, c = i - qi * 9;
        float4 qv = *(const float4*)&g_qf[(bh * Lc + qrow[qi]) * DIMc + c * 4];
        Qs[(c * 4 + 0) * QSTR + qi] = qv.x * (1.0f / 6.0f);
        Qs[(c * 4 + 1) * QSTR + qi] = qv.y * (1.0f / 6.0f);
        Qs[(c * 4 + 2) * QSTR + qi] = qv.z * (1.0f / 6.0f);
        Qs[(c * 4 + 3) * QSTR + qi] = qv.w * (1.0f / 6.0f);
    }

    float m0 = -3.0e38f, m1 = -3.0e38f;
    float l0 = 0.0f, l1 = 0.0f;
    float o0[3] = {0.f, 0.f, 0.f};
    float o1[3] = {0.f, 0.f, 0.f};

    for (int t = 0; t < 8; t++) {
        const int k0 = t * FKT;
        __syncthreads();   // Qs ready (t=0) / prior PV done reading Ps,Vs

        // stage K transposed + V natural
        for (int i = tid; i < FKT * 9; i += 256) {
            int ki = i / 9, c = i - ki * 9;
            int k = k0 + ki;
            float4 kv = make_float4(0.f, 0.f, 0.f, 0.f);
            float4 vv = make_float4(0.f, 0.f, 0.f, 0.f);
            if (k < Lc) {
                kv = *(const float4*)&g_kf[(bh * Lc + k) * DIMc + c * 4];
                vv = *(const float4*)&g_vf[(bh * Lc + k) * DIMc + c * 4];
            }
            Ks[(c * 4 + 0) * KSTR + ki] = kv.x;
            Ks[(c * 4 + 1) * KSTR + ki] = kv.y;
            Ks[(c * 4 + 2) * KSTR + ki] = kv.z;
            Ks[(c * 4 + 3) * KSTR + ki] = kv.w;
            *(float4*)&Vs[ki * VSTR + c * 4] = vv;
        }
        __syncthreads();

        // ---- S phase: 2 q x 8 k per thread ----
        float s0[8], s1[8];
#pragma unroll
        for (int j = 0; j < 8; j++) { s0[j] = 0.f; s1[j] = 0.f; }
#pragma unroll
        for (int d = 0; d < 36; d++) {
            float2 a2 = *(const float2*)&Qs[d * QSTR + ty * 2];
            float4 b0 = *(const float4*)&Ks[d * KSTR + tx * 8];
            float4 b1 = *(const float4*)&Ks[d * KSTR + tx * 8 + 4];
            float br[8] = {b0.x, b0.y, b0.z, b0.w, b1.x, b1.y, b1.z, b1.w};
#pragma unroll
            for (int j = 0; j < 8; j++) {
                s0[j] += a2.x * br[j];
                s1[j] += a2.y * br[j];
            }
        }
        if (k0 + FKT > Lc) {
#pragma unroll
            for (int j = 0; j < 8; j++)
                if (k0 + tx * 8 + j >= Lc) { s0[j] = -3.0e38f; s1[j] = -3.0e38f; }
        }

        // tile row-max via 16-lane butterfly
        float mt0 = s0[0], mt1 = s1[0];
#pragma unroll
        for (int j = 1; j < 8; j++) {
            mt0 = fmaxf(mt0, s0[j]);
            mt1 = fmaxf(mt1, s1[j]);
        }
#pragma unroll
        for (int o = 8; o; o >>= 1) {
            mt0 = fmaxf(mt0, __shfl_xor_sync(0xffffffffu, mt0, o));
            mt1 = fmaxf(mt1, __shfl_xor_sync(0xffffffffu, mt1, o));
        }
        float nm0 = fmaxf(m0, mt0), nm1 = fmaxf(m1, mt1);
        float rs0 = __expf(m0 - nm0), rs1 = __expf(m1 - nm1);

        float ps0 = 0.f, ps1 = 0.f;
#pragma unroll
        for (int j = 0; j < 8; j++) {
            float p0 = __expf(s0[j] - nm0);
            float p1 = __expf(s1[j] - nm1);
            ps0 += p0; ps1 += p1;
            Ps[(tx * 8 + j) * PSTR + ty * 2]     = p0;
            Ps[(tx * 8 + j) * PSTR + ty * 2 + 1] = p1;
        }
#pragma unroll
        for (int o = 8; o; o >>= 1) {
            ps0 += __shfl_xor_sync(0xffffffffu, ps0, o);
            ps1 += __shfl_xor_sync(0xffffffffu, ps1, o);
        }
        l0 = l0 * rs0 + ps0;  m0 = nm0;
        l1 = l1 * rs1 + ps1;  m1 = nm1;
        __syncthreads();

        // ---- PV phase: 2 q x 3 d per thread (tx < 12) ----
        if (tx < 12) {
#pragma unroll
            for (int c = 0; c < 3; c++) { o0[c] *= rs0; o1[c] *= rs1; }
            const float* vb = &Vs[tx * 3];
#pragma unroll 4
            for (int kk = 0; kk < FKT; kk++) {
                float2 p2 = *(const float2*)&Ps[kk * PSTR + ty * 2];
                float v0 = vb[kk * VSTR + 0];
                float v1 = vb[kk * VSTR + 1];
                float v2 = vb[kk * VSTR + 2];
                o0[0] += p2.x * v0; o0[1] += p2.x * v1; o0[2] += p2.x * v2;
                o1[0] += p2.y * v0; o1[1] += p2.y * v1; o1[2] += p2.y * v2;
            }
        }
    }

    // ---- epilogue: scale by 1/l, scatter ----
    if (tx < 12) {
        float i0 = 1.0f / l0, i1 = 1.0f / l1;
        int b = bh >> 3, h = bh & 7;
        int qa = q0 + ty * 2;
        int qb = qa + 1;
        if (qa < NQc) {
            float* dst = &g_attn[((long)b * Lc + qrow[ty * 2]) * Dc + h * 36 + tx * 3];
            dst[0] = o0[0] * i0; dst[1] = o0[1] * i0; dst[2] = o0[2] * i0;
        }
        if (qb < NQc) {
            float* dst = &g_attn[((long)b * Lc + qrow[ty * 2 + 1]) * Dc + h * 36 + tx * 3];
            dst[0] = o1[0] * i1; dst[1] = o1[1] * i1; dst[2] = o1[2] * i1;
        }
    }
}

// ---------------------------------------------------------------------------
// V mean per (bh), deterministic tree reduction. grid 16, 256 threads.
// ---------------------------------------------------------------------------
__global__ void __launch_bounds__(256) vmean_kernel()
{
    const int bh  = blockIdx.x;
    const int tid = threadIdx.x;
    float acc[36];
#pragma unroll
    for (int d = 0; d < 36; d++) acc[d] = 0.0f;

    for (int l = tid; l < Lc; l += 256) {
        const float* vp = &g_vf[(bh * Lc + l) * DIMc];
#pragma unroll
        for (int d = 0; d < 36; d++) acc[d] += vp[d];
    }
#pragma unroll
    for (int d = 0; d < 36; d++) {
#pragma unroll
        for (int o = 16; o; o >>= 1) acc[d] += __shfl_xor_sync(0xffffffffu, acc[d], o);
    }
    __shared__ float sm[8][36];
    if ((tid & 31) == 0) {
        int w = tid >> 5;
#pragma unroll
        for (int d = 0; d < 36; d++) sm[w][d] = acc[d];
    }
    __syncthreads();
    if (tid < 36) {
        float t = 0.0f;
#pragma unroll
        for (int w = 0; w < 8; w++) t += sm[w][tid];
        g_vmean[bh * DIMc + tid] = t * (1.0f / (float)Lc);
    }
}

// Fill attn output with per-head mean(V)
__global__ void __launch_bounds__(256) fill_kernel()
{
    int i = blockIdx.x * 256 + threadIdx.x;
    if (i >= Bc * Lc * Dc) return;
    int d  = i % Dc;
    int bl = i / Dc;
    int b  = bl / Lc;
    int hh = d / 36;
    int dd = d - hh * 36;
    g_attn[i] = g_vmean[(b * Hc + hh) * DIMc + dd];
}

// ---------------------------------------------------------------------------
// LayerNorm over D=288: out = LN(a + b). WHICH 0: a=x(param), out=g_h1f.
// WHICH 1: a=g_f2f, b=g_h1f, out=param. grid 2000, 288 threads.
// ---------------------------------------------------------------------------
template <int WHICH>
__global__ void __launch_bounds__(288) ln_kernel(
    const float* __restrict__ xin, float* __restrict__ oout,
    const float* __restrict__ gg, const float* __restrict__ bb)
{
    const int r = blockIdx.x;
    const int d = threadIdx.x;
    const int base = r * Dc;

    float v;
    if (WHICH == 0) v = xin[base + d] + g_attn[base + d];
    else            v = g_f2f[base + d] + g_h1f[base + d];

    __shared__ float red[9];
    __shared__ float s_mu, s_rs;

    float s = v;
#pragma unroll
    for (int o = 16; o; o >>= 1) s += __shfl_xor_sync(0xffffffffu, s, o);
    if ((d & 31) == 0) red[d >> 5] = s;
    __syncthreads();
    if (d == 0) {
        float t = 0.0f;
        for (int i = 0; i < 9; i++) t += red[i];
        s_mu = t * (1.0f / (float)Dc);
    }
    __syncthreads();

    float dv = v - s_mu;
    float qv = dv * dv;
#pragma unroll
    for (int o = 16; o; o >>= 1) qv += __shfl_xor_sync(0xffffffffu, qv, o);
    if ((d & 31) == 0) red[d >> 5] = qv;
    __syncthreads();
    if (d == 0) {
        float t = 0.0f;
        for (int i = 0; i < 9; i++) t += red[i];
        s_rs = rsqrtf(t * (1.0f / (float)Dc) + 1e-5f);
    }
    __syncthreads();

    float outv = dv * s_rs * gg[d] + bb[d];
    if (WHICH == 0) g_h1f[base + d] = outv;
    else            oout[base + d]  = outv;
}

// ---------------------------------------------------------------------------
extern "C" void kernel_launch(void* const* d_in, const int* in_sizes, int n_in,
                              void* d_out, int out_size)
{
    (void)in_sizes; (void)n_in; (void)out_size;
    const float* x   = (const float*)d_in[0];
    const int*   ik  = (const int*)d_in[1];
    const float* Wq  = (const float*)d_in[2];
    const float* bq  = (const float*)d_in[3];
    const float* Wk  = (const float*)d_in[4];
    const float* bk  = (const float*)d_in[5];
    const float* Wv  = (const float*)d_in[6];
    const float* bv  = (const float*)d_in[7];
    const float* W1  = (const float*)d_in[8];
    const float* b1  = (const float*)d_in[9];
    const float* W2  = (const float*)d_in[10];
    const float* b2  = (const float*)d_in[11];
    const float* g1  = (const float*)d_in[12];
    const float* be1 = (const float*)d_in[13];
    const float* g2  = (const float*)d_in[14];
    const float* be2 = (const float*)d_in[15];
    float* out = (float*)d_out;

    const int measure_smem = Lc * DIMc * (int)sizeof(float);  // 144 KB
    cudaFuncSetAttribute(measure_kernel,
                         cudaFuncAttributeMaxDynamicSharedMemorySize, measure_smem);
    cudaFuncSetAttribute(fattn_kernel,
                         cudaFuncAttributeMaxDynamicSharedMemorySize, FATTN_SMEM);

    // 1) QKV projections (N=864, K=288): 9x16 = 144 blocks = 1 wave
    gemm4<0, 96><<<dim3(864 / 96, (Mrows + 127) / 128), 256>>>(
        x, Mrows, 864, Dc, Wq, Wk, Wv, bq, bk, bv);

    // 2) sparsity measure: 9x16 = 144 blocks
    measure_kernel<<<dim3(9, BHc), 256, measure_smem>>>(ik);

    // 3) top-250 active queries per (b,h)
    topk_kernel<<<BHc, 512>>>();

    // 4) mean(V) + lazy fill (before fused attention scatters active rows)
    vmean_kernel<<<BHc, 256>>>();
    fill_kernel<<<(Bc * Lc * Dc + 255) / 256, 256>>>();

    // 5) fused sim+softmax+AV+scatter: (8, 16) = 128 blocks
    fattn_kernel<<<dim3((NQc + FQT - 1) / FQT, BHc), 256, FATTN_SMEM>>>();

    // 6) residual + LN1
    ln_kernel<0><<<Mrows, 288>>>(x, nullptr, g1, be1);

    // 7) FFN (exact GELU both layers): 9x16 = 144 blocks each
    gemm4<1, 64><<<dim3(DFFc / 64, (Mrows + 127) / 128), 256>>>(
        nullptr, Mrows, DFFc, Dc, W1, nullptr, nullptr, nullptr, b1, nullptr);
    gemm4<2, 32><<<dim3(Dc / 32, (Mrows + 127) / 128), 256>>>(
        nullptr, Mrows, Dc, DFFc, W2, nullptr, nullptr, nullptr, b2, nullptr);

    // 8) residual + LN2 -> output
    ln_kernel<1><<<Mrows, 288>>>(nullptr, out, g2, be2);
}

// round 6
// speedup vs baseline: 1.7267x; 1.0434x over previous
#include <cuda_runtime.h>
#include <math.h>

// Problem constants
constexpr int Bc   = 2;
constexpr int Lc   = 1000;
constexpr int Dc   = 288;
constexpr int Hc   = 8;
constexpr int DIMc = 36;
constexpr int DFFc = 576;
constexpr int KSc  = 250;
constexpr int NQc  = 250;
constexpr int BHc  = Bc * Hc;      // 16
constexpr int Mrows = Bc * Lc;     // 2000

// Scratch (static device globals; no allocation)
__device__ float g_qf[BHc * Lc * DIMc];
__device__ float g_kf[BHc * Lc * DIMc];
__device__ float g_vf[BHc * Lc * DIMc];
__device__ float g_measure[BHc * Lc];
__device__ int   g_idxq[BHc * NQc];
__device__ float g_vmean[BHc * DIMc];
__device__ float g_vpart[16 * 2 * 288];          // [by][b][vcol] V col partials
__device__ int   g_iks[Lc * KSc];                // bucketed sampled indices
__device__ int   g_ikoff[Lc * 8];                // per-row bucket start offsets
__device__ float g_attn[Bc * Lc * Dc];
__device__ float g_h1f[Bc * Lc * Dc];
__device__ float g_f1f[Bc * Lc * DFFc];
__device__ float g_f2f[Bc * Lc * Dc];

__device__ __forceinline__ float gelu_exact(float x) {
    return 0.5f * x * (1.0f + erff(x * 0.7071067811865475f));
}

// ---------------------------------------------------------------------------
// Bucket prep: stable-sort each row of index_key by (idx & 7).
// Warp per row; ballot-based stable ranks. Grid 125 x 256.
// ---------------------------------------------------------------------------
__global__ void __launch_bounds__(256) bucket_kernel(const int* __restrict__ ik)
{
    int row  = blockIdx.x * 8 + (threadIdx.x >> 5);
    int lane = threadIdx.x & 31;
    if (row >= Lc) return;
    const int* src = &ik[row * KSc];

    int vals[8];
    int cnt[8] = {0, 0, 0, 0, 0, 0, 0, 0};
#pragma unroll
    for (int c = 0; c < 8; c++) {
        int j = lane + c * 32;
        int v = (j < KSc) ? src[j] : -1;
        vals[c] = v;
        int b = v & 7;
#pragma unroll
        for (int bk = 0; bk < 8; bk++) {
            unsigned m = __ballot_sync(0xffffffffu, v >= 0 && b == bk);
            cnt[bk] += __popc(m);
        }
    }
    int off[8];
    int run = 0;
#pragma unroll
    for (int bk = 0; bk < 8; bk++) { off[bk] = run; run += cnt[bk]; }
    if (lane < 8) g_ikoff[row * 8 + lane] = off[lane];

    int base[8];
#pragma unroll
    for (int bk = 0; bk < 8; bk++) base[bk] = off[bk];
#pragma unroll
    for (int c = 0; c < 8; c++) {
        int v = vals[c];
        int b = v & 7;
        int pos = 0;
#pragma unroll
        for (int bk = 0; bk < 8; bk++) {
            unsigned m = __ballot_sync(0xffffffffu, v >= 0 && b == bk);
            if (v >= 0 && b == bk)
                pos = base[bk] + __popc(m & ((1u << lane) - 1u));
            base[bk] += __popc(m);
        }
        if (v >= 0) g_iks[row * KSc + pos] = v;
    }
}

// ---------------------------------------------------------------------------
// Tiled GEMM with 2-stage smem double buffering (1 sync per k-tile):
// MODE 0: QKV (N=864 : Wq|Wk|Wv), scatter to g_qf/g_kf/g_vf; V-col partial
//         sums -> g_vpart (vmean fused).
// MODE 1: FFN1: A=g_h1f, gelu -> g_f1f
// MODE 2: FFN2: A=g_f1f, gelu -> g_f2f
// ---------------------------------------------------------------------------
template <int MODE, int BN>
__global__ void __launch_bounds__(256) gemm4(
    const float* __restrict__ A_in, int M, int N, int K,
    const float* __restrict__ W0, const float* __restrict__ W1p,
    const float* __restrict__ W2p,
    const float* __restrict__ b0, const float* __restrict__ b1p,
    const float* __restrict__ b2p)
{
    constexpr int TN   = BN / 16;
    constexpr int BSTR = BN + 4;
    constexpr int NB   = BN / 16;

    const float* A = (MODE == 0) ? A_in : (MODE == 1 ? g_h1f : g_f1f);

    __shared__ __align__(16) float As[2][16][132];
    __shared__ __align__(16) float Bs[2][16][BSTR];

    const int m0 = blockIdx.y * 128;
    const int n0 = blockIdx.x * BN;
    const int tid = threadIdx.x;
    const int tx = tid & 15;
    const int ty = tid >> 4;

    float acc[8][TN];
#pragma unroll
    for (int i = 0; i < 8; i++)
#pragma unroll
        for (int j = 0; j < TN; j++) acc[i][j] = 0.0f;

    float a_r[8], b_r[NB];

    auto load_tile = [&](int kt) {
        const int k0 = kt * 16;
#pragma unroll
        for (int p = 0; p < 8; p++) {
            int i  = tid + p * 256;
            int kk = i & 15;
            int mi = i >> 4;
            int r  = m0 + mi;
            a_r[p] = (r < M) ? A[r * K + k0 + kk] : 0.0f;
        }
#pragma unroll
        for (int p = 0; p < NB; p++) {
            int i  = tid + p * 256;
            int kk = i & 15;
            int nc = i >> 4;
            int col = n0 + nc;
            float wv;
            if (MODE == 0) {
                const float* w; int cc;
                if (col < 288)      { w = W0;  cc = col; }
                else if (col < 576) { w = W1p; cc = col - 288; }
                else                { w = W2p; cc = col - 576; }
                wv = w[cc * K + k0 + kk];
            } else {
                wv = W0[col * K + k0 + kk];
            }
            b_r[p] = wv;
        }
    };
    auto store_tile = [&](int buf) {
#pragma unroll
        for (int p = 0; p < 8; p++) {
            int i  = tid + p * 256;
            As[buf][i & 15][i >> 4] = a_r[p];
        }
#pragma unroll
        for (int p = 0; p < NB; p++) {
            int i  = tid + p * 256;
            Bs[buf][i & 15][i >> 4] = b_r[p];
        }
    };

    const int ktiles = K / 16;
    load_tile(0);
    store_tile(0);
    __syncthreads();

    for (int kt = 0; kt < ktiles; kt++) {
        const int cur = kt & 1;
        if (kt + 1 < ktiles) load_tile(kt + 1);

#pragma unroll
        for (int kk = 0; kk < 16; kk++) {
            float a8[8];
            float4 a0 = *(const float4*)&As[cur][kk][ty * 8];
            float4 a1 = *(const float4*)&As[cur][kk][ty * 8 + 4];
            a8[0] = a0.x; a8[1] = a0.y; a8[2] = a0.z; a8[3] = a0.w;
            a8[4] = a1.x; a8[5] = a1.y; a8[6] = a1.z; a8[7] = a1.w;
            float bv[TN];
            if (TN == 6) {
#pragma unroll
                for (int c = 0; c < 3; c++) {
                    float2 b2v = *(const float2*)&Bs[cur][kk][tx * 6 + 2 * c];
                    bv[2 * c] = b2v.x; bv[2 * c + 1] = b2v.y;
                }
            } else if (TN == 4) {
                float4 b4 = *(const float4*)&Bs[cur][kk][tx * 4];
                bv[0] = b4.x; bv[1] = b4.y; bv[2] = b4.z; bv[3] = b4.w;
            } else {
                float2 b2v = *(const float2*)&Bs[cur][kk][tx * 2];
                bv[0] = b2v.x; bv[1] = b2v.y;
            }
#pragma unroll
            for (int i = 0; i < 8; i++)
#pragma unroll
                for (int j = 0; j < TN; j++) acc[i][j] += a8[i] * bv[j];
        }

        if (kt + 1 < ktiles) store_tile((kt + 1) & 1);
        __syncthreads();
    }

    float ps0[TN], ps1[TN];
#pragma unroll
    for (int j = 0; j < TN; j++) { ps0[j] = 0.0f; ps1[j] = 0.0f; }

#pragma unroll
    for (int i = 0; i < 8; i++) {
        int r = m0 + ty * 8 + i;
        if (r >= M) continue;
#pragma unroll
        for (int j = 0; j < TN; j++) {
            int col = n0 + tx * TN + j;
            float v = acc[i][j];
            if (MODE == 0) {
                int cc; const float* bias; float* dst;
                if (col < 288)      { cc = col;       bias = b0;  dst = g_qf; }
                else if (col < 576) { cc = col - 288; bias = b1p; dst = g_kf; }
                else                { cc = col - 576; bias = b2p; dst = g_vf; }
                v += bias[cc];
                int h  = cc / 36;
                int dd = cc - h * 36;
                int bb = r / Lc;
                int ll = r - bb * Lc;
                dst[((bb * Hc + h) * Lc + ll) * DIMc + dd] = v;
                if (col >= 576) {
                    if (bb == 0) ps0[j] += v; else ps1[j] += v;
                }
            } else {
                v = gelu_exact(v + b1p[col]);
                if (MODE == 1) g_f1f[r * N + col] = v;
                else           g_f2f[r * N + col] = v;
            }
        }
    }

    // V column partial sums (blocks covering cols 576..863 only)
    if (MODE == 0 && n0 >= 576) {
        float* vred = (float*)As;   // reuse: [2][16][96]
#pragma unroll
        for (int j = 0; j < TN; j++) {
            vred[(0 * 16 + ty) * 96 + tx * TN + j] = ps0[j];
            vred[(1 * 16 + ty) * 96 + tx * TN + j] = ps1[j];
        }
        __syncthreads();
        if (tid < 192) {
            int b = tid / 96, c = tid - (tid / 96) * 96;
            float s = 0.0f;
#pragma unroll
            for (int t = 0; t < 16; t++) s += vred[(b * 16 + t) * 96 + c];
            g_vpart[(blockIdx.y * 2 + b) * 288 + (n0 - 576 + c)] = s;
        }
    }
}

// ---------------------------------------------------------------------------
// Measure: measure[bh][l] = max_j q.k[idx] - sum_j(q.k[idx]) / L
// Bucketed gather: lane (p = lane&7) handles keys with idx%8==p so every
// 8-lane LDS.128 phase hits distinct bank-quads (stride 9 f4, 9%8==1).
// ---------------------------------------------------------------------------
__global__ void __launch_bounds__(256) measure_kernel()
{
    extern __shared__ __align__(16) float ks[];   // [Lc][36]
    const int chunk = blockIdx.x;
    const int bh    = blockIdx.y;
    const int tid   = threadIdx.x;

    const float4* ksrc4 = (const float4*)&g_kf[bh * Lc * DIMc];
    float4* kdst4 = (float4*)ks;
    for (int i = tid; i < Lc * DIMc / 4; i += 256) kdst4[i] = ksrc4[i];
    __syncthreads();

    const int warp = tid >> 5;
    const int lane = tid & 31;
    const int p = lane & 7;
    const int s = lane >> 3;
    const int lstart = chunk * 112;
    const int lend   = min(lstart + 112, Lc);

    for (int l = lstart + warp; l < lend; l += 8) {
        float4 q4[9];
        const float4* qp = (const float4*)&g_qf[(bh * Lc + l) * DIMc];
#pragma unroll
        for (int c = 0; c < 9; c++) q4[c] = qp[c];

        int off0 = g_ikoff[l * 8 + p];
        int end0 = (p < 7) ? g_ikoff[l * 8 + p + 1] : KSc;

        float mx = -3.4e38f;
        float sm = 0.0f;
        for (int j = off0 + s; j < end0; j += 4) {
            int idx = g_iks[l * KSc + j];
            const float4* kp = (const float4*)&ks[idx * DIMc];
            float accd = 0.0f;
#pragma unroll
            for (int c = 0; c < 9; c++) {
                float4 kv = kp[c];
                accd += q4[c].x * kv.x + q4[c].y * kv.y
                      + q4[c].z * kv.z + q4[c].w * kv.w;
            }
            mx = fmaxf(mx, accd);
            sm += accd;
        }
#pragma unroll
        for (int o = 16; o; o >>= 1) {
            mx = fmaxf(mx, __shfl_xor_sync(0xffffffffu, mx, o));
            sm += __shfl_xor_sync(0xffffffffu, sm, o);
        }
        if (lane == 0) g_measure[bh * Lc + l] = mx - sm * (1.0f / (float)Lc);
    }
}

// ---------------------------------------------------------------------------
// TopK (+ vmean reduce tail): bitonic sort of packed u64 keys.
// ---------------------------------------------------------------------------
__global__ void __launch_bounds__(512) topk_kernel()
{
    __shared__ unsigned long long keys[1024];
    const int bh  = blockIdx.x;
    const int tid = threadIdx.x;

    for (int i = tid; i < 1024; i += 512) {
        unsigned long long kv = 0ULL;
        if (i < Lc) {
            float f = g_measure[bh * Lc + i];
            unsigned u = __float_as_uint(f);
            u = (u & 0x80000000u) ? ~u : (u | 0x80000000u);
            kv = ((unsigned long long)u << 32) | (unsigned)(~i);
        }
        keys[i] = kv;
    }
    __syncthreads();

    for (int k = 2; k <= 1024; k <<= 1) {
        for (int j = k >> 1; j > 0; j >>= 1) {
#pragma unroll
            for (int w = 0; w < 2; w++) {
                int i   = tid + w * 512;
                int ixj = i ^ j;
                if (ixj > i) {
                    bool descend = ((i & k) == 0);
                    unsigned long long a = keys[i];
                    unsigned long long b = keys[ixj];
                    bool sw = descend ? (a < b) : (a > b);
                    if (sw) { keys[i] = b; keys[ixj] = a; }
                }
            }
            __syncthreads();
        }
    }

    if (tid < NQc) {
        unsigned low = (unsigned)keys[tid];
        g_idxq[bh * NQc + tid] = (int)(~low);
    }

    // vmean reduce (fused): 16 row-tile partials, fixed order
    if (tid < DIMc) {
        int b = bh >> 3, h = bh & 7;
        float sv = 0.0f;
#pragma unroll
        for (int t = 0; t < 16; t++)
            sv += g_vpart[(t * 2 + b) * 288 + h * 36 + tid];
        g_vmean[bh * DIMc + tid] = sv * (1.0f / (float)Lc);
    }
}

// ---------------------------------------------------------------------------
// Fused attention (unchanged from R5): 32 selected queries x all keys,
// online softmax, direct scatter with 1/l scale.
// ---------------------------------------------------------------------------
constexpr int FQT  = 32;
constexpr int FKT  = 128;
constexpr int QSTR = 34;
constexpr int KSTR = 132;
constexpr int VSTR = 48;
constexpr int PSTR = 34;
constexpr int FATTN_SMEM =
    (36 * QSTR + 36 * KSTR + FKT * VSTR + FKT * PSTR) * (int)sizeof(float) + 256;

__global__ void __launch_bounds__(256) fattn_kernel()
{
    extern __shared__ __align__(16) float smem[];
    float* Qs = smem;                        // [36][QSTR]
    float* Ks = Qs + 36 * QSTR;              // [36][KSTR]
    float* Vs = Ks + 36 * KSTR;              // [FKT][VSTR]
    float* Ps = Vs + FKT * VSTR;             // [FKT][PSTR]
    int*   qrow = (int*)(Ps + FKT * PSTR);   // [FQT]

    const int bh = blockIdx.y;
    const int q0 = blockIdx.x * FQT;
    const int tid = threadIdx.x;
    const int tx = tid & 15;
    const int ty = tid >> 4;

    if (tid < FQT) {
        int q = q0 + tid;
        qrow[tid] = g_idxq[bh * NQc + (q < NQc ? q : 0)];
    }
    for (int i = tid; i < FKT * 3; i += 256) {
        int r = i / 3, c = 36 + (i % 3) * 4;
        *(float4*)&Vs[r * VSTR + c] = make_float4(0.f, 0.f, 0.f, 0.f);
    }
    __syncthreads();

    for (int i = tid; i < FQT * 9; i += 256) {
        int qi = i / 9, c = i - qi * 9;
        float4 qv = *(const float4*)&g_qf[(bh * Lc + qrow[qi]) * DIMc + c * 4];
        Qs[(c * 4 + 0) * QSTR + qi] = qv.x * (1.0f / 6.0f);
        Qs[(c * 4 + 1) * QSTR + qi] = qv.y * (1.0f / 6.0f);
        Qs[(c * 4 + 2) * QSTR + qi] = qv.z * (1.0f / 6.0f);
        Qs[(c * 4 + 3) * QSTR + qi] = qv.w * (1.0f / 6.0f);
    }

    float m0 = -3.0e38f, m1 = -3.0e38f;
    float l0 = 0.0f, l1 = 0.0f;
    float o0[3] = {0.f, 0.f, 0.f};
    float o1[3] = {0.f, 0.f, 0.f};

    for (int t = 0; t < 8; t++) {
        const int k0 = t * FKT;
        __syncthreads();

        for (int i = tid; i < FKT * 9; i += 256) {
            int ki = i / 9, c = i - ki * 9;
            int k = k0 + ki;
            float4 kv = make_float4(0.f, 0.f, 0.f, 0.f);
            float4 vv = make_float4(0.f, 0.f, 0.f, 0.f);
            if (k < Lc) {
                kv = *(const float4*)&g_kf[(bh * Lc + k) * DIMc + c * 4];
                vv = *(const float4*)&g_vf[(bh * Lc + k) * DIMc + c * 4];
            }
            Ks[(c * 4 + 0) * KSTR + ki] = kv.x;
            Ks[(c * 4 + 1) * KSTR + ki] = kv.y;
            Ks[(c * 4 + 2) * KSTR + ki] = kv.z;
            Ks[(c * 4 + 3) * KSTR + ki] = kv.w;
            *(float4*)&Vs[ki * VSTR + c * 4] = vv;
        }
        __syncthreads();

        float s0[8], s1[8];
#pragma unroll
        for (int j = 0; j < 8; j++) { s0[j] = 0.f; s1[j] = 0.f; }
#pragma unroll
        for (int d = 0; d < 36; d++) {
            float2 a2 = *(const float2*)&Qs[d * QSTR + ty * 2];
            float4 b0 = *(const float4*)&Ks[d * KSTR + tx * 8];
            float4 b1 = *(const float4*)&Ks[d * KSTR + tx * 8 + 4];
            float br[8] = {b0.x, b0.y, b0.z, b0.w, b1.x, b1.y, b1.z, b1.w};
#pragma unroll
            for (int j = 0; j < 8; j++) {
                s0[j] += a2.x * br[j];
                s1[j] += a2.y * br[j];
            }
        }
        if (k0 + FKT > Lc) {
#pragma unroll
            for (int j = 0; j < 8; j++)
                if (k0 + tx * 8 + j >= Lc) { s0[j] = -3.0e38f; s1[j] = -3.0e38f; }
        }

        float mt0 = s0[0], mt1 = s1[0];
#pragma unroll
        for (int j = 1; j < 8; j++) {
            mt0 = fmaxf(mt0, s0[j]);
            mt1 = fmaxf(mt1, s1[j]);
        }
#pragma unroll
        for (int o = 8; o; o >>= 1) {
            mt0 = fmaxf(mt0, __shfl_xor_sync(0xffffffffu, mt0, o));
            mt1 = fmaxf(mt1, __shfl_xor_sync(0xffffffffu, mt1, o));
        }
        float nm0 = fmaxf(m0, mt0), nm1 = fmaxf(m1, mt1);
        float rs0 = __expf(m0 - nm0), rs1 = __expf(m1 - nm1);

        float ps0 = 0.f, ps1 = 0.f;
#pragma unroll
        for (int j = 0; j < 8; j++) {
            float p0 = __expf(s0[j] - nm0);
            float p1 = __expf(s1[j] - nm1);
            ps0 += p0; ps1 += p1;
            Ps[(tx * 8 + j) * PSTR + ty * 2]     = p0;
            Ps[(tx * 8 + j) * PSTR + ty * 2 + 1] = p1;
        }
#pragma unroll
        for (int o = 8; o; o >>= 1) {
            ps0 += __shfl_xor_sync(0xffffffffu, ps0, o);
            ps1 += __shfl_xor_sync(0xffffffffu, ps1, o);
        }
        l0 = l0 * rs0 + ps0;  m0 = nm0;
        l1 = l1 * rs1 + ps1;  m1 = nm1;
        __syncthreads();

        if (tx < 12) {
#pragma unroll
            for (int c = 0; c < 3; c++) { o0[c] *= rs0; o1[c] *= rs1; }
            const float* vb = &Vs[tx * 3];
#pragma unroll 4
            for (int kk = 0; kk < FKT; kk++) {
                float2 p2 = *(const float2*)&Ps[kk * PSTR + ty * 2];
                float v0 = vb[kk * VSTR + 0];
                float v1 = vb[kk * VSTR + 1];
                float v2 = vb[kk * VSTR + 2];
                o0[0] += p2.x * v0; o0[1] += p2.x * v1; o0[2] += p2.x * v2;
                o1[0] += p2.y * v0; o1[1] += p2.y * v1; o1[2] += p2.y * v2;
            }
        }
    }

    if (tx < 12) {
        float i0 = 1.0f / l0, i1 = 1.0f / l1;
        int b = bh >> 3, h = bh & 7;
        int qa = q0 + ty * 2;
        int qb = qa + 1;
        if (qa < NQc) {
            float* dst = &g_attn[((long)b * Lc + qrow[ty * 2]) * Dc + h * 36 + tx * 3];
            dst[0] = o0[0] * i0; dst[1] = o0[1] * i0; dst[2] = o0[2] * i0;
        }
        if (qb < NQc) {
            float* dst = &g_attn[((long)b * Lc + qrow[ty * 2 + 1]) * Dc + h * 36 + tx * 3];
            dst[0] = o1[0] * i1; dst[1] = o1[1] * i1; dst[2] = o1[2] * i1;
        }
    }
}

// Fill attn output with per-head mean(V)
__global__ void __launch_bounds__(256) fill_kernel()
{
    int i = blockIdx.x * 256 + threadIdx.x;
    if (i >= Bc * Lc * Dc) return;
    int d  = i % Dc;
    int bl = i / Dc;
    int b  = bl / Lc;
    int hh = d / 36;
    int dd = d - hh * 36;
    g_attn[i] = g_vmean[(b * Hc + hh) * DIMc + dd];
}

// ---------------------------------------------------------------------------
// LayerNorm, warp-per-row (288 = 32 x 9). Grid 250, 256 threads.
// WHICH 0: LN(x + attn) -> g_h1f.  WHICH 1: LN(f2f + h1f) -> out.
// ---------------------------------------------------------------------------
template <int WHICH>
__global__ void __launch_bounds__(256) ln_kernel(
    const float* __restrict__ xin, float* __restrict__ oout,
    const float* __restrict__ gg, const float* __restrict__ bb)
{
    const int r = blockIdx.x * 8 + (threadIdx.x >> 5);
    const int lane = threadIdx.x & 31;
    const int base = r * Dc;

    float v[9];
#pragma unroll
    for (int c = 0; c < 9; c++) {
        int d = lane + c * 32;
        if (WHICH == 0) v[c] = xin[base + d] + g_attn[base + d];
        else            v[c] = g_f2f[base + d] + g_h1f[base + d];
    }
    float s = 0.0f;
#pragma unroll
    for (int c = 0; c < 9; c++) s += v[c];
#pragma unroll
    for (int o = 16; o; o >>= 1) s += __shfl_xor_sync(0xffffffffu, s, o);
    float mu = s * (1.0f / (float)Dc);

    float q = 0.0f;
#pragma unroll
    for (int c = 0; c < 9; c++) { float dv = v[c] - mu; q += dv * dv; }
#pragma unroll
    for (int o = 16; o; o >>= 1) q += __shfl_xor_sync(0xffffffffu, q, o);
    float rs = rsqrtf(q * (1.0f / (float)Dc) + 1e-5f);

#pragma unroll
    for (int c = 0; c < 9; c++) {
        int d = lane + c * 32;
        float outv = (v[c] - mu) * rs * gg[d] + bb[d];
        if (WHICH == 0) g_h1f[base + d] = outv;
        else            oout[base + d]  = outv;
    }
}

// ---------------------------------------------------------------------------
extern "C" void kernel_launch(void* const* d_in, const int* in_sizes, int n_in,
                              void* d_out, int out_size)
{
    (void)in_sizes; (void)n_in; (void)out_size;
    const float* x   = (const float*)d_in[0];
    const int*   ik  = (const int*)d_in[1];
    const float* Wq  = (const float*)d_in[2];
    const float* bq  = (const float*)d_in[3];
    const float* Wk  = (const float*)d_in[4];
    const float* bk  = (const float*)d_in[5];
    const float* Wv  = (const float*)d_in[6];
    const float* bv  = (const float*)d_in[7];
    const float* W1  = (const float*)d_in[8];
    const float* b1  = (const float*)d_in[9];
    const float* W2  = (const float*)d_in[10];
    const float* b2  = (const float*)d_in[11];
    const float* g1  = (const float*)d_in[12];
    const float* be1 = (const float*)d_in[13];
    const float* g2  = (const float*)d_in[14];
    const float* be2 = (const float*)d_in[15];
    float* out = (float*)d_out;

    const int measure_smem = Lc * DIMc * (int)sizeof(float);  // 144 KB
    cudaFuncSetAttribute(measure_kernel,
                         cudaFuncAttributeMaxDynamicSharedMemorySize, measure_smem);
    cudaFuncSetAttribute(fattn_kernel,
                         cudaFuncAttributeMaxDynamicSharedMemorySize, FATTN_SMEM);

    // 0) bucket index_key rows by idx%8 (depends only on ik)
    bucket_kernel<<<125, 256>>>(ik);

    // 1) QKV projections + fused V partial sums: 9x16 = 144 blocks
    gemm4<0, 96><<<dim3(864 / 96, (Mrows + 127) / 128), 256>>>(
        x, Mrows, 864, Dc, Wq, Wk, Wv, bq, bk, bv);

    // 2) sparsity measure (bucketed, conflict-free): 9x16 = 144 blocks
    measure_kernel<<<dim3(9, BHc), 256, measure_smem>>>();

    // 3) top-250 active queries per (b,h) + vmean reduce
    topk_kernel<<<BHc, 512>>>();

    // 4) lazy fill with mean(V)
    fill_kernel<<<(Bc * Lc * Dc + 255) / 256, 256>>>();

    // 5) fused sim+softmax+AV+scatter: (8, 16) = 128 blocks
    fattn_kernel<<<dim3((NQc + FQT - 1) / FQT, BHc), 256, FATTN_SMEM>>>();

    // 6) residual + LN1 (warp per row)
    ln_kernel<0><<<Mrows / 8, 256>>>(x, nullptr, g1, be1);

    // 7) FFN (exact GELU both layers): 9x16 = 144 blocks each
    gemm4<1, 64><<<dim3(DFFc / 64, (Mrows + 127) / 128), 256>>>(
        nullptr, Mrows, DFFc, Dc, W1, nullptr, nullptr, nullptr, b1, nullptr);
    gemm4<2, 32><<<dim3(Dc / 32, (Mrows + 127) / 128), 256>>>(
        nullptr, Mrows, Dc, DFFc, W2, nullptr, nullptr, nullptr, b2, nullptr);

    // 8) residual + LN2 -> output
    ln_kernel<1><<<Mrows / 8, 256>>>(nullptr, out, g2, be2);
}